// round 3
// baseline (speedup 1.0000x reference)
#include <cuda_runtime.h>
#include <cuda_fp16.h>
#include <cstdint>

// Problem constants
#define BB   128   // batch
#define TT   512   // timesteps
#define II   64    // input dim
#define HH   1024  // hidden
#define GG   4096  // 4*H gates
#define OO   64    // output dim

#define KC   64    // K chunk
#define NT   32    // N tile per block
#define ASTR 72    // padded smem row stride (halfs)
#define NB   130   // persistent grid size

// ---------------- scratch (static device globals; no runtime alloc) ----------------
__device__ __align__(128) __half d_Wc1[GG * 1088];        // gate-interleaved [x|h1] weights
__device__ __align__(128) __half d_Wc2[GG * 2048];        // gate-interleaved [h1|h2] weights
__device__ __align__(128) __half d_Wo [OO * HH];          // output proj weights
__device__ __align__(128) float  d_bc1[GG];
__device__ __align__(128) float  d_bc2[GG];
__device__ __align__(128) __half d_Xc [BB * TT * II];     // fp16 inputs
__device__ __align__(128) __half d_HB [2 * BB * 2048];    // ping-pong [h1|h2] state, fp16
__device__ __align__(128) float  d_C1 [BB * HH];
__device__ __align__(128) float  d_C2 [BB * HH];
__device__ unsigned g_bar;

// ---------------- init / convert kernel ----------------
__global__ void init_kernel(const float* __restrict__ x,
                            const float* __restrict__ Wih1, const float* __restrict__ Whh1,
                            const float* __restrict__ bih1, const float* __restrict__ bhh1,
                            const float* __restrict__ Wih2, const float* __restrict__ Whh2,
                            const float* __restrict__ bih2, const float* __restrict__ bhh2,
                            const float* __restrict__ Wout)
{
    long tid = (long)blockIdx.x * blockDim.x + threadIdx.x;
    long stride = (long)gridDim.x * blockDim.x;
    if (tid == 0) g_bar = 0u;

    for (long idx = tid; idx < (long)GG * 1088; idx += stride) {
        int row = (int)(idx / 1088), k = (int)(idx % 1088);
        int j = row >> 2, g_ = row & 3;
        int sj = g_ * HH + j;
        float v = (k < II) ? Wih1[(long)sj * II + k] : Whh1[(long)sj * HH + (k - II)];
        d_Wc1[idx] = __float2half(v);
    }
    for (long idx = tid; idx < (long)GG * 2048; idx += stride) {
        int row = (int)(idx / 2048), k = (int)(idx % 2048);
        int j = row >> 2, g_ = row & 3;
        int sj = g_ * HH + j;
        float v = (k < HH) ? Wih2[(long)sj * HH + k] : Whh2[(long)sj * HH + (k - HH)];
        d_Wc2[idx] = __float2half(v);
    }
    for (long idx = tid; idx < GG; idx += stride) {
        int row = (int)idx;
        int j = row >> 2, g_ = row & 3;
        int sj = g_ * HH + j;
        d_bc1[row] = bih1[sj] + bhh1[sj];
        d_bc2[row] = bih2[sj] + bhh2[sj];
    }
    for (long idx = tid; idx < (long)OO * HH; idx += stride)
        d_Wo[idx] = __float2half(Wout[idx]);
    for (long idx = tid; idx < (long)BB * TT * II; idx += stride)
        d_Xc[idx] = __float2half(x[idx]);
    for (long idx = tid; idx < (long)2 * BB * 2048; idx += stride)
        d_HB[idx] = __float2half(0.f);
    for (long idx = tid; idx < (long)BB * HH; idx += stride) {
        d_C1[idx] = 0.f;
        d_C2[idx] = 0.f;
    }
}

// ---------------- helpers ----------------
__device__ __forceinline__ void cp16(uint32_t smem_dst, const void* gsrc) {
    asm volatile("cp.async.cg.shared.global [%0], [%1], 16;\n" :: "r"(smem_dst), "l"(gsrc));
}
__device__ __forceinline__ void cp_commit() { asm volatile("cp.async.commit_group;\n"); }
template <int N> __device__ __forceinline__ void cp_wait() {
    asm volatile("cp.async.wait_group %0;\n" :: "n"(N));
}
__device__ __forceinline__ void mma16816(float* c, const uint32_t* a, uint32_t b0, uint32_t b1) {
    asm volatile(
        "mma.sync.aligned.m16n8k16.row.col.f32.f16.f16.f32 "
        "{%0,%1,%2,%3}, {%4,%5,%6,%7}, {%8,%9}, {%0,%1,%2,%3};\n"
        : "+f"(c[0]), "+f"(c[1]), "+f"(c[2]), "+f"(c[3])
        : "r"(a[0]), "r"(a[1]), "r"(a[2]), "r"(a[3]), "r"(b0), "r"(b1));
}
__device__ __forceinline__ float sigmoidf_(float v) { return 1.f / (1.f + expf(-v)); }

// software grid barrier (all NB blocks co-resident)
__device__ __forceinline__ void grid_barrier(unsigned target) {
    __threadfence();
    __syncthreads();
    if (threadIdx.x == 0) {
        atomicAdd(&g_bar, 1u);
        while (*(volatile unsigned*)&g_bar < target) { }
    }
    __syncthreads();
    __threadfence();
}

// ---------------- one GEMM tile + epilogue (block-level) ----------------
// mode: 0 = layer1 gates, 1 = layer2 gates, 2 = y projection (for step t-1)
__device__ void do_tile(int mode, int t, int n0,
                        __half* A_s,   // [2][128*ASTR]
                        __half* B_s,   // [2][NT*ASTR]
                        const float* __restrict__ b_out, float* __restrict__ out)
{
    const int p = t & 1, q = p ^ 1;
    const int tid = threadIdx.x;

    const __half* Wbase;
    int Wstride, Ktot;
    if (mode == 2)      { Wbase = d_Wo;  Wstride = HH;   Ktot = HH;   }
    else if (mode == 0) { Wbase = d_Wc1; Wstride = 1088; Ktot = 1088; }
    else                { Wbase = d_Wc2; Wstride = 2048; Ktot = 2048; }
    const int nc = Ktot / KC;

    auto a_src = [&](int c, int& astr) -> const __half* {
        const int k0 = c * KC;
        if (mode == 2) { astr = 2048; return d_HB + q * (BB * 2048) + HH + k0; }
        if (mode == 0) {
            if (c == 0) { astr = TT * II; return d_Xc + t * II; }
            astr = 2048; return d_HB + q * (BB * 2048) + (k0 - II);
        }
        astr = 2048;
        return d_HB + ((k0 < HH) ? p : q) * (BB * 2048) + k0;
    };

    auto load_chunk = [&](int c, int buf) {
        int astr;
        const __half* Ab = a_src(c, astr);
        const int k0 = c * KC;
        __half* As = A_s + buf * (128 * ASTR);
        __half* Bs = B_s + buf * (NT * ASTR);
#pragma unroll
        for (int i = 0; i < 4; i++) {
            int seg = tid + i * 256;
            int r = seg >> 3, c16 = seg & 7;
            const __half* src = Ab + (long)r * astr + c16 * 8;
            uint32_t dst = (uint32_t)__cvta_generic_to_shared(&As[r * ASTR + c16 * 8]);
            cp16(dst, src);
        }
        {
            int r = tid >> 3, c16 = tid & 7;
            const __half* src = Wbase + (long)(n0 + r) * Wstride + k0 + c16 * 8;
            uint32_t dst = (uint32_t)__cvta_generic_to_shared(&Bs[r * ASTR + c16 * 8]);
            cp16(dst, src);
        }
        cp_commit();
    };

    const int warp = tid >> 5, lane = tid & 31;
    const int wm = warp & 3, wn = warp >> 2;     // 4 warps along M, 2 along N
    const int g  = lane >> 2, tg = lane & 3;

    float acc[2][2][4];
#pragma unroll
    for (int a = 0; a < 2; a++)
#pragma unroll
        for (int b = 0; b < 2; b++)
#pragma unroll
            for (int k = 0; k < 4; k++) acc[a][b][k] = 0.f;

    load_chunk(0, 0);
    for (int c = 0; c < nc; c++) {
        if (c + 1 < nc) { load_chunk(c + 1, (c + 1) & 1); cp_wait<1>(); }
        else            { cp_wait<0>(); }
        __syncthreads();

        const __half* Ab = A_s + (c & 1) * (128 * ASTR);
        const __half* Bb = B_s + (c & 1) * (NT * ASTR);
#pragma unroll
        for (int kk = 0; kk < 4; kk++) {
            uint32_t a[2][4];
#pragma unroll
            for (int mt = 0; mt < 2; mt++) {
                int r = wm * 32 + mt * 16 + g;
                const __half* base = Ab + r * ASTR + kk * 16 + 2 * tg;
                a[mt][0] = *(const uint32_t*)(base);
                a[mt][1] = *(const uint32_t*)(base + 8 * ASTR);
                a[mt][2] = *(const uint32_t*)(base + 8);
                a[mt][3] = *(const uint32_t*)(base + 8 * ASTR + 8);
            }
#pragma unroll
            for (int nt = 0; nt < 2; nt++) {
                int nrow = wn * 16 + nt * 8 + g;
                const __half* bb = Bb + nrow * ASTR + kk * 16 + 2 * tg;
                uint32_t b0 = *(const uint32_t*)(bb);
                uint32_t b1 = *(const uint32_t*)(bb + 8);
#pragma unroll
                for (int mt = 0; mt < 2; mt++) mma16816(acc[mt][nt], a[mt], b0, b1);
            }
        }
        __syncthreads();
    }

    // ---- epilogue via shared (aliased over A_s buffer 0) ----
    float* Gs = (float*)A_s;   // [128][36] fp32 = 18432B, fits in A_s buffer 0
#pragma unroll
    for (int mt = 0; mt < 2; mt++)
#pragma unroll
        for (int nt = 0; nt < 2; nt++) {
            int r = wm * 32 + mt * 16 + g;
            int ncol = wn * 16 + nt * 8 + 2 * tg;
            Gs[r * 36 + ncol]           = acc[mt][nt][0];
            Gs[r * 36 + ncol + 1]       = acc[mt][nt][1];
            Gs[(r + 8) * 36 + ncol]     = acc[mt][nt][2];
            Gs[(r + 8) * 36 + ncol + 1] = acc[mt][nt][3];
        }
    __syncthreads();

    if (mode == 2) {
        const int tm1 = t - 1;
#pragma unroll
        for (int i = 0; i < 16; i++) {
            int e = tid + i * 256;
            int b = e >> 5, n = e & 31;
            out[((long)b * TT + tm1) * OO + n0 + n] = Gs[b * 36 + n] + b_out[n0 + n];
        }
        return;
    }

    const float* bc = (mode == 0) ? d_bc1 : d_bc2;
    float* C        = (mode == 0) ? d_C1 : d_C2;
    const int hoff  = (mode == 0) ? 0 : HH;
    const int jbase = n0 >> 2;
#pragma unroll
    for (int i = 0; i < 4; i++) {
        int e = tid + i * 256;
        int b = e >> 3, uu = e & 7;
        float gi = Gs[b * 36 + 4 * uu + 0] + bc[n0 + 4 * uu + 0];
        float gf = Gs[b * 36 + 4 * uu + 1] + bc[n0 + 4 * uu + 1];
        float gg = Gs[b * 36 + 4 * uu + 2] + bc[n0 + 4 * uu + 2];
        float go = Gs[b * 36 + 4 * uu + 3] + bc[n0 + 4 * uu + 3];
        float iv = sigmoidf_(gi);
        float fv = sigmoidf_(gf);
        float gv = tanhf(gg);
        float ov = sigmoidf_(go);
        int j = jbase + uu;
        float cold = C[b * HH + j];
        float cn = fv * cold + iv * gv;
        C[b * HH + j] = cn;
        float h = ov * tanhf(cn);
        d_HB[p * (BB * 2048) + b * 2048 + hoff + j] = __float2half(h);
    }
}

// ---------------- persistent kernel: whole sequence in one launch ----------------
__global__ __launch_bounds__(256)
void lstm_persistent(const float* __restrict__ b_out, float* __restrict__ out)
{
    __shared__ __half A_s[2 * 128 * ASTR];
    __shared__ __half B_s[2 * NT * ASTR];

    const int bx = blockIdx.x;
    unsigned target = 0;

    for (int t = 0; t <= TT; t++) {
        // phase A: layer1 gates for step t (blocks 0..127), y(t-1) (blocks 128..129)
        if (bx < 128) {
            if (t < TT) do_tile(0, t, bx * NT, A_s, B_s, b_out, out);
        } else {
            if (t > 0)  do_tile(2, t, (bx - 128) * NT, A_s, B_s, b_out, out);
        }
        target += NB;
        grid_barrier(target);

        // phase B: layer2 gates for step t
        if (t < TT) {
            if (bx < 128) do_tile(1, t, bx * NT, A_s, B_s, b_out, out);
            target += NB;
            grid_barrier(target);
        }
    }
}

// ---------------- launch ----------------
extern "C" void kernel_launch(void* const* d_in, const int* in_sizes, int n_in,
                              void* d_out, int out_size)
{
    const float* x     = (const float*)d_in[0];
    const float* Wih1  = (const float*)d_in[1];
    const float* Whh1  = (const float*)d_in[2];
    const float* bih1  = (const float*)d_in[3];
    const float* bhh1  = (const float*)d_in[4];
    const float* Wih2  = (const float*)d_in[5];
    const float* Whh2  = (const float*)d_in[6];
    const float* bih2  = (const float*)d_in[7];
    const float* bhh2  = (const float*)d_in[8];
    const float* Wout  = (const float*)d_in[9];
    const float* bout  = (const float*)d_in[10];
    float* out = (float*)d_out;

    init_kernel<<<1024, 256>>>(x, Wih1, Whh1, bih1, bhh1, Wih2, Whh2, bih2, bhh2, Wout);
    lstm_persistent<<<NB, 256>>>(bout, out);
}

// round 7
// speedup vs baseline: 1.2295x; 1.2295x over previous
#include <cuda_runtime.h>
#include <cuda_fp16.h>
#include <cstdint>

// Problem constants
#define BB   128   // batch
#define TT   512   // timesteps
#define II   64    // input dim
#define HH   1024  // hidden
#define GG   4096  // 4*H gates
#define OO   64    // output dim

#define KC    64   // K chunk (halfs)
#define NT    64   // N tile per block
#define ASTR  72   // padded smem row stride (halfs)
#define NSTG  4    // pipeline stages
#define NB    129  // persistent grid size
#define NTHR  512

#define STAGE_HALFS (192 * ASTR)          // A(128 rows) + B(64 rows)
#define SMEM_BYTES  (NSTG * STAGE_HALFS * 2)

// ---------------- scratch ----------------
__device__ __align__(128) __half d_Wc1[GG * 1088];   // gate-interleaved [x|h1]
__device__ __align__(128) __half d_Wc2[GG * 2048];   // gate-interleaved [h1|h2]
__device__ __align__(128) __half d_Wo [OO * HH];
__device__ __align__(128) float  d_bc1[GG];
__device__ __align__(128) float  d_bc2[GG];
__device__ __align__(128) __half d_Xc [BB * TT * II];
__device__ __align__(128) __half d_H1 [2 * BB * HH];
__device__ __align__(128) __half d_H2 [2 * BB * HH];
__device__ __align__(128) float  d_C1 [BB * HH];
__device__ __align__(128) float  d_C2 [BB * HH];
__device__ unsigned g_bar;

// ---------------- init ----------------
__global__ void init_kernel(const float* __restrict__ x,
                            const float* __restrict__ Wih1, const float* __restrict__ Whh1,
                            const float* __restrict__ bih1, const float* __restrict__ bhh1,
                            const float* __restrict__ Wih2, const float* __restrict__ Whh2,
                            const float* __restrict__ bih2, const float* __restrict__ bhh2,
                            const float* __restrict__ Wout)
{
    long tid = (long)blockIdx.x * blockDim.x + threadIdx.x;
    long stride = (long)gridDim.x * blockDim.x;
    if (tid == 0) g_bar = 0u;

    for (long idx = tid; idx < (long)GG * 1088; idx += stride) {
        int row = (int)(idx / 1088), k = (int)(idx % 1088);
        int j = row >> 2, g_ = row & 3;
        int sj = g_ * HH + j;
        float v = (k < II) ? Wih1[(long)sj * II + k] : Whh1[(long)sj * HH + (k - II)];
        d_Wc1[idx] = __float2half(v);
    }
    for (long idx = tid; idx < (long)GG * 2048; idx += stride) {
        int row = (int)(idx / 2048), k = (int)(idx % 2048);
        int j = row >> 2, g_ = row & 3;
        int sj = g_ * HH + j;
        float v = (k < HH) ? Wih2[(long)sj * HH + k] : Whh2[(long)sj * HH + (k - HH)];
        d_Wc2[idx] = __float2half(v);
    }
    for (long idx = tid; idx < GG; idx += stride) {
        int row = (int)idx;
        int j = row >> 2, g_ = row & 3;
        int sj = g_ * HH + j;
        d_bc1[row] = bih1[sj] + bhh1[sj];
        d_bc2[row] = bih2[sj] + bhh2[sj];
    }
    for (long idx = tid; idx < (long)OO * HH; idx += stride)
        d_Wo[idx] = __float2half(Wout[idx]);
    for (long idx = tid; idx < (long)BB * TT * II; idx += stride)
        d_Xc[idx] = __float2half(x[idx]);
    for (long idx = tid; idx < (long)2 * BB * HH; idx += stride) {
        d_H1[idx] = __float2half(0.f);
        d_H2[idx] = __float2half(0.f);
    }
    for (long idx = tid; idx < (long)BB * HH; idx += stride) {
        d_C1[idx] = 0.f;
        d_C2[idx] = 0.f;
    }
}

// ---------------- helpers ----------------
__device__ __forceinline__ void cp16(uint32_t smem_dst, const void* gsrc) {
    asm volatile("cp.async.cg.shared.global [%0], [%1], 16;\n" :: "r"(smem_dst), "l"(gsrc));
}
__device__ __forceinline__ void cp_commit() { asm volatile("cp.async.commit_group;\n"); }
template <int N> __device__ __forceinline__ void cp_wait() {
    asm volatile("cp.async.wait_group %0;\n" :: "n"(N));
}
__device__ __forceinline__ void ldsm_x4(uint32_t* r, uint32_t addr) {
    asm volatile("ldmatrix.sync.aligned.m8n8.x4.shared.b16 {%0,%1,%2,%3}, [%4];"
                 : "=r"(r[0]), "=r"(r[1]), "=r"(r[2]), "=r"(r[3]) : "r"(addr));
}
__device__ __forceinline__ void mma16816(float* c, const uint32_t* a, uint32_t b0, uint32_t b1) {
    asm volatile(
        "mma.sync.aligned.m16n8k16.row.col.f32.f16.f16.f32 "
        "{%0,%1,%2,%3}, {%4,%5,%6,%7}, {%8,%9}, {%0,%1,%2,%3};\n"
        : "+f"(c[0]), "+f"(c[1]), "+f"(c[2]), "+f"(c[3])
        : "r"(a[0]), "r"(a[1]), "r"(a[2]), "r"(a[3]), "r"(b0), "r"(b1));
}
__device__ __forceinline__ float sigmoidf_(float v) { return 1.f / (1.f + expf(-v)); }

__device__ __forceinline__ void grid_barrier(unsigned target) {
    __threadfence();
    __syncthreads();
    if (threadIdx.x == 0) {
        atomicAdd(&g_bar, 1u);
        while (*(volatile unsigned*)&g_bar < target) { }
    }
    __syncthreads();
    __threadfence();
}

// ---------------- one GEMM tile + epilogue ----------------
// mode 0: layer1 gates, step t      (K=1088 : [x_t | h1(t-1)])
// mode 1: layer2 gates, step s      (K=2048 : [h1(s) | h2(s-1)])
// mode 2: y projection, step u      (K=1024 : h2(u)), NT=64 covers all of O
__device__ void do_tile(int mode, int step, int n0, __half* smem,
                        const float* __restrict__ b_out, float* __restrict__ out)
{
    const int tid = threadIdx.x;
    const __half* Wbase;
    int Wstride, Ktot;
    if (mode == 2)      { Wbase = d_Wo;  Wstride = HH;   Ktot = HH;   }
    else if (mode == 0) { Wbase = d_Wc1; Wstride = 1088; Ktot = 1088; }
    else                { Wbase = d_Wc2; Wstride = 2048; Ktot = 2048; }
    const int nc = Ktot / KC;
    const int par = step & 1, parq = par ^ 1;

    auto a_src = [&](int c, int& astr) -> const __half* {
        const int k0 = c * KC;
        if (mode == 2) { astr = HH; return d_H2 + par * (BB * HH) + k0; }
        if (mode == 0) {
            if (c == 0) { astr = TT * II; return d_Xc + step * II; }
            astr = HH; return d_H1 + parq * (BB * HH) + (k0 - II);
        }
        astr = HH;
        if (k0 < HH) return d_H1 + par  * (BB * HH) + k0;          // h1(s)
        else         return d_H2 + parq * (BB * HH) + (k0 - HH);   // h2(s-1)
    };

    auto load_chunk = [&](int c, int buf) {
        int astr;
        const __half* Ab = a_src(c, astr);
        const int k0 = c * KC;
        __half* As = smem + buf * STAGE_HALFS;
        __half* Bs = As + 128 * ASTR;
#pragma unroll
        for (int i = 0; i < 2; i++) {
            int seg = tid + i * NTHR;            // 1024 segs: 128 rows x 8
            int r = seg >> 3, c16 = seg & 7;
            cp16((uint32_t)__cvta_generic_to_shared(&As[r * ASTR + c16 * 8]),
                 Ab + (long)r * astr + c16 * 8);
        }
        {
            int r = tid >> 3, c16 = tid & 7;     // 512 segs: 64 rows x 8
            cp16((uint32_t)__cvta_generic_to_shared(&Bs[r * ASTR + c16 * 8]),
                 Wbase + (long)(n0 + r) * Wstride + k0 + c16 * 8);
        }
        cp_commit();
    };

    const int warp = tid >> 5, lane = tid & 31;
    const int wm = warp & 7, wn = warp >> 3;     // 8 warps M x 2 warps N
    const int g  = lane >> 2, tg = lane & 3;
    const int mat = lane >> 3, r8 = lane & 7;

    // ldmatrix lane-address offsets (halfs, within stage)
    const int aoff = (wm * 16 + (mat & 1) * 8 + r8) * ASTR + (mat >> 1) * 8;
    const int boff0 = 128 * ASTR + (wn * 32 +      (mat >> 1) * 8 + r8) * ASTR + (mat & 1) * 8;
    const int boff1 = 128 * ASTR + (wn * 32 + 16 + (mat >> 1) * 8 + r8) * ASTR + (mat & 1) * 8;

    float acc[4][4];
#pragma unroll
    for (int i = 0; i < 4; i++)
#pragma unroll
        for (int k = 0; k < 4; k++) acc[i][k] = 0.f;

    load_chunk(0, 0); load_chunk(1, 1); load_chunk(2, 2);

    for (int c = 0; c < nc; c++) {
        cp_wait<2>();
        __syncthreads();
        if (c + 3 < nc) load_chunk(c + 3, (c + 3) & 3);

        const __half* stg = smem + (c & 3) * STAGE_HALFS;
        uint32_t abase = (uint32_t)__cvta_generic_to_shared(stg + aoff);
        uint32_t bbase0 = (uint32_t)__cvta_generic_to_shared(stg + boff0);
        uint32_t bbase1 = (uint32_t)__cvta_generic_to_shared(stg + boff1);
#pragma unroll
        for (int kk = 0; kk < 4; kk++) {
            uint32_t a[4], b0[4], b1[4];
            ldsm_x4(a,  abase  + kk * 32);
            ldsm_x4(b0, bbase0 + kk * 32);
            ldsm_x4(b1, bbase1 + kk * 32);
            mma16816(acc[0], a, b0[0], b0[1]);
            mma16816(acc[1], a, b0[2], b0[3]);
            mma16816(acc[2], a, b1[0], b1[1]);
            mma16816(acc[3], a, b1[2], b1[3]);
        }
    }
    cp_wait<0>();
    __syncthreads();

    // ---- epilogue via shared fp32 [128][72] aliased over stage buffers ----
    float* Gs = (float*)smem;
#pragma unroll
    for (int nt = 0; nt < 4; nt++) {
        int ncol = wn * 32 + nt * 8 + 2 * tg;
        int r0 = wm * 16 + g;
        Gs[r0 * ASTR + ncol]           = acc[nt][0];
        Gs[r0 * ASTR + ncol + 1]       = acc[nt][1];
        Gs[(r0 + 8) * ASTR + ncol]     = acc[nt][2];
        Gs[(r0 + 8) * ASTR + ncol + 1] = acc[nt][3];
    }
    __syncthreads();

    if (mode == 2) {
#pragma unroll
        for (int i = 0; i < 16; i++) {
            int e = tid + i * NTHR;
            int b = e >> 6, n = e & 63;
            out[((long)b * TT + step) * OO + n] = Gs[b * ASTR + n] + b_out[n];
        }
        return;
    }

    const float* bc = (mode == 0) ? d_bc1 : d_bc2;
    float* C        = (mode == 0) ? d_C1 : d_C2;
    __half* Hdst    = ((mode == 0) ? d_H1 : d_H2) + par * (BB * HH);
    const int jbase = n0 >> 2;
#pragma unroll
    for (int i = 0; i < 4; i++) {
        int e = tid + i * NTHR;                  // 2048 unit-slots
        int b = e >> 4, uu = e & 15;
        const float* gq = Gs + b * ASTR + 4 * uu;
        float gi = gq[0] + bc[n0 + 4 * uu + 0];
        float gf = gq[1] + bc[n0 + 4 * uu + 1];
        float gg = gq[2] + bc[n0 + 4 * uu + 2];
        float go = gq[3] + bc[n0 + 4 * uu + 3];
        float iv = sigmoidf_(gi);
        float fv = sigmoidf_(gf);
        float gv = tanhf(gg);
        float ov = sigmoidf_(go);
        int j = jbase + uu;
        float cold = C[b * HH + j];
        float cn = fv * cold + iv * gv;
        C[b * HH + j] = cn;
        Hdst[b * HH + j] = __float2half(ov * tanhf(cn));
    }
}

// ---------------- persistent kernel ----------------
// Phase P(t): layer1(t) [bx 0..63] || layer2(t-1) [bx 64..127] || y(t-2) [bx 128]
__global__ __launch_bounds__(NTHR, 1)
void lstm_persistent(const float* __restrict__ b_out, float* __restrict__ out)
{
    extern __shared__ __half smem[];
    const int bx = blockIdx.x;
    unsigned target = 0;

    for (int t = 0; t <= TT + 1; t++) {
        if (bx < 64) {
            if (t < TT) do_tile(0, t, bx * NT, smem, b_out, out);
        } else if (bx < 128) {
            if (t >= 1 && t <= TT) do_tile(1, t - 1, (bx - 64) * NT, smem, b_out, out);
        } else {
            if (t >= 2) do_tile(2, t - 2, 0, smem, b_out, out);
        }
        target += NB;
        grid_barrier(target);
    }
}

// ---------------- launch ----------------
extern "C" void kernel_launch(void* const* d_in, const int* in_sizes, int n_in,
                              void* d_out, int out_size)
{
    const float* x     = (const float*)d_in[0];
    const float* Wih1  = (const float*)d_in[1];
    const float* Whh1  = (const float*)d_in[2];
    const float* bih1  = (const float*)d_in[3];
    const float* bhh1  = (const float*)d_in[4];
    const float* Wih2  = (const float*)d_in[5];
    const float* Whh2  = (const float*)d_in[6];
    const float* bih2  = (const float*)d_in[7];
    const float* bhh2  = (const float*)d_in[8];
    const float* Wout  = (const float*)d_in[9];
    const float* bout  = (const float*)d_in[10];
    float* out = (float*)d_out;

    cudaFuncSetAttribute(lstm_persistent,
                         cudaFuncAttributeMaxDynamicSharedMemorySize, SMEM_BYTES);

    init_kernel<<<1024, 256>>>(x, Wih1, Whh1, bih1, bhh1, Wih2, Whh2, bih2, bhh2, Wout);
    lstm_persistent<<<NB, NTHR, SMEM_BYTES>>>(bout, out);
}

// round 8
// speedup vs baseline: 1.2414x; 1.0097x over previous
#include <cuda_runtime.h>
#include <cuda_fp16.h>
#include <cstdint>

// Problem constants
#define BB   128
#define TT   512
#define II   64
#define HH   1024
#define GG   4096
#define OO   64

#define KC    64   // K chunk (halfs)
#define NT    64   // N tile per block
#define ASTR  72   // padded smem row stride (halfs)
#define NSTG  4
#define NB    129
#define NTHR  256  // 8 warps: 4 along M x 2 along N, warp tile 32x32

#define STAGE_HALFS (192 * ASTR)          // A(128 rows) + B(64 rows)
#define SMEM_BYTES  (NSTG * STAGE_HALFS * 2)

// ---------------- scratch ----------------
__device__ __align__(128) __half d_Wc1[GG * 1088];
__device__ __align__(128) __half d_Wc2[GG * 2048];
__device__ __align__(128) __half d_Wo [OO * HH];
__device__ __align__(128) float  d_bc1[GG];
__device__ __align__(128) float  d_bc2[GG];
__device__ __align__(128) __half d_Xc [BB * TT * II];
__device__ __align__(128) __half d_H1 [2 * BB * HH];
__device__ __align__(128) __half d_H2 [2 * BB * HH];
__device__ __align__(128) float  d_C1 [BB * HH];
__device__ __align__(128) float  d_C2 [BB * HH];
__device__ unsigned g_bar;

// ---------------- init ----------------
__global__ void init_kernel(const float* __restrict__ x,
                            const float* __restrict__ Wih1, const float* __restrict__ Whh1,
                            const float* __restrict__ bih1, const float* __restrict__ bhh1,
                            const float* __restrict__ Wih2, const float* __restrict__ Whh2,
                            const float* __restrict__ bih2, const float* __restrict__ bhh2,
                            const float* __restrict__ Wout)
{
    long tid = (long)blockIdx.x * blockDim.x + threadIdx.x;
    long stride = (long)gridDim.x * blockDim.x;
    if (tid == 0) g_bar = 0u;

    for (long idx = tid; idx < (long)GG * 1088; idx += stride) {
        int row = (int)(idx / 1088), k = (int)(idx % 1088);
        int j = row >> 2, g_ = row & 3;
        int sj = g_ * HH + j;
        float v = (k < II) ? Wih1[(long)sj * II + k] : Whh1[(long)sj * HH + (k - II)];
        d_Wc1[idx] = __float2half(v);
    }
    for (long idx = tid; idx < (long)GG * 2048; idx += stride) {
        int row = (int)(idx / 2048), k = (int)(idx % 2048);
        int j = row >> 2, g_ = row & 3;
        int sj = g_ * HH + j;
        float v = (k < HH) ? Wih2[(long)sj * HH + k] : Whh2[(long)sj * HH + (k - HH)];
        d_Wc2[idx] = __float2half(v);
    }
    for (long idx = tid; idx < GG; idx += stride) {
        int row = (int)idx;
        int j = row >> 2, g_ = row & 3;
        int sj = g_ * HH + j;
        d_bc1[row] = bih1[sj] + bhh1[sj];
        d_bc2[row] = bih2[sj] + bhh2[sj];
    }
    for (long idx = tid; idx < (long)OO * HH; idx += stride)
        d_Wo[idx] = __float2half(Wout[idx]);
    for (long idx = tid; idx < (long)BB * TT * II; idx += stride)
        d_Xc[idx] = __float2half(x[idx]);
    for (long idx = tid; idx < (long)2 * BB * HH; idx += stride) {
        d_H1[idx] = __float2half(0.f);
        d_H2[idx] = __float2half(0.f);
    }
    for (long idx = tid; idx < (long)BB * HH; idx += stride) {
        d_C1[idx] = 0.f;
        d_C2[idx] = 0.f;
    }
}

// ---------------- helpers ----------------
__device__ __forceinline__ void cp16(uint32_t smem_dst, const void* gsrc) {
    asm volatile("cp.async.cg.shared.global [%0], [%1], 16;\n" :: "r"(smem_dst), "l"(gsrc));
}
__device__ __forceinline__ void cp_commit() { asm volatile("cp.async.commit_group;\n"); }
template <int N> __device__ __forceinline__ void cp_wait() {
    asm volatile("cp.async.wait_group %0;\n" :: "n"(N));
}
__device__ __forceinline__ void ldsm_x4(uint32_t* r, uint32_t addr) {
    asm volatile("ldmatrix.sync.aligned.m8n8.x4.shared.b16 {%0,%1,%2,%3}, [%4];"
                 : "=r"(r[0]), "=r"(r[1]), "=r"(r[2]), "=r"(r[3]) : "r"(addr));
}
__device__ __forceinline__ void mma16816(float* c, const uint32_t* a, uint32_t b0, uint32_t b1) {
    asm volatile(
        "mma.sync.aligned.m16n8k16.row.col.f32.f16.f16.f32 "
        "{%0,%1,%2,%3}, {%4,%5,%6,%7}, {%8,%9}, {%0,%1,%2,%3};\n"
        : "+f"(c[0]), "+f"(c[1]), "+f"(c[2]), "+f"(c[3])
        : "r"(a[0]), "r"(a[1]), "r"(a[2]), "r"(a[3]), "r"(b0), "r"(b1));
}
__device__ __forceinline__ float sigmoidf_(float v) { return 1.f / (1.f + expf(-v)); }

__device__ __forceinline__ void grid_barrier(unsigned target) {
    __threadfence();
    __syncthreads();
    if (threadIdx.x == 0) {
        atomicAdd(&g_bar, 1u);
        while (*(volatile unsigned*)&g_bar < target) { }
    }
    __syncthreads();
    __threadfence();
}

// ---------------- one GEMM tile + epilogue ----------------
// mode 0: layer1 gates (K=1088), mode 1: layer2 gates (K=2048), mode 2: y (K=1024)
__device__ void do_tile(int mode, int step, int n0, __half* smem,
                        const float* __restrict__ b_out, float* __restrict__ out)
{
    const int tid = threadIdx.x;
    const __half* Wbase;
    int Wstride, Ktot;
    if (mode == 2)      { Wbase = d_Wo;  Wstride = HH;   Ktot = HH;   }
    else if (mode == 0) { Wbase = d_Wc1; Wstride = 1088; Ktot = 1088; }
    else                { Wbase = d_Wc2; Wstride = 2048; Ktot = 2048; }
    const int nc = Ktot / KC;
    const int par = step & 1, parq = par ^ 1;

    auto a_src = [&](int c, int& astr) -> const __half* {
        const int k0 = c * KC;
        if (mode == 2) { astr = HH; return d_H2 + par * (BB * HH) + k0; }
        if (mode == 0) {
            if (c == 0) { astr = TT * II; return d_Xc + step * II; }
            astr = HH; return d_H1 + parq * (BB * HH) + (k0 - II);
        }
        astr = HH;
        if (k0 < HH) return d_H1 + par  * (BB * HH) + k0;
        else         return d_H2 + parq * (BB * HH) + (k0 - HH);
    };

    auto load_chunk = [&](int c, int buf) {
        int astr;
        const __half* Ab = a_src(c, astr);
        const int k0 = c * KC;
        __half* As = smem + buf * STAGE_HALFS;
        __half* Bs = As + 128 * ASTR;
#pragma unroll
        for (int i = 0; i < 4; i++) {
            int seg = tid + i * NTHR;            // 1024 segs: 128 rows x 8
            int r = seg >> 3, c16 = seg & 7;
            cp16((uint32_t)__cvta_generic_to_shared(&As[r * ASTR + c16 * 8]),
                 Ab + (long)r * astr + c16 * 8);
        }
#pragma unroll
        for (int i = 0; i < 2; i++) {
            int seg = tid + i * NTHR;            // 512 segs: 64 rows x 8
            int r = seg >> 3, c16 = seg & 7;
            cp16((uint32_t)__cvta_generic_to_shared(&Bs[r * ASTR + c16 * 8]),
                 Wbase + (long)(n0 + r) * Wstride + k0 + c16 * 8);
        }
        cp_commit();
    };

    const int warp = tid >> 5, lane = tid & 31;
    const int wm = warp & 3, wn = warp >> 2;     // 4 warps M x 2 warps N; warp tile 32x32
    const int g  = lane >> 2, tg = lane & 3;
    const int mat = lane >> 3, r8 = lane & 7;

    // ldmatrix lane-address offsets (halfs, within stage)
    const int aoff0 = (wm * 32 +      (mat & 1) * 8 + r8) * ASTR + (mat >> 1) * 8;
    const int aoff1 = (wm * 32 + 16 + (mat & 1) * 8 + r8) * ASTR + (mat >> 1) * 8;
    const int boff0 = 128 * ASTR + (wn * 32 +      (mat >> 1) * 8 + r8) * ASTR + (mat & 1) * 8;
    const int boff1 = 128 * ASTR + (wn * 32 + 16 + (mat >> 1) * 8 + r8) * ASTR + (mat & 1) * 8;

    float acc[2][4][4];
#pragma unroll
    for (int i = 0; i < 2; i++)
#pragma unroll
        for (int j = 0; j < 4; j++)
#pragma unroll
            for (int k = 0; k < 4; k++) acc[i][j][k] = 0.f;

    load_chunk(0, 0); load_chunk(1, 1); load_chunk(2, 2);

    for (int c = 0; c < nc; c++) {
        cp_wait<2>();
        __syncthreads();
        if (c + 3 < nc) load_chunk(c + 3, (c + 3) & 3);

        const __half* stg = smem + (c & 3) * STAGE_HALFS;
        uint32_t a0b = (uint32_t)__cvta_generic_to_shared(stg + aoff0);
        uint32_t a1b = (uint32_t)__cvta_generic_to_shared(stg + aoff1);
        uint32_t b0b = (uint32_t)__cvta_generic_to_shared(stg + boff0);
        uint32_t b1b = (uint32_t)__cvta_generic_to_shared(stg + boff1);

        // register double-buffered fragment pipeline over kk
        uint32_t fa0[2][4], fa1[2][4], fb0[2][4], fb1[2][4];
        ldsm_x4(fa0[0], a0b); ldsm_x4(fa1[0], a1b);
        ldsm_x4(fb0[0], b0b); ldsm_x4(fb1[0], b1b);
#pragma unroll
        for (int kk = 0; kk < 4; kk++) {
            int cur = kk & 1, nxt = cur ^ 1;
            if (kk < 3) {
                ldsm_x4(fa0[nxt], a0b + (kk + 1) * 32);
                ldsm_x4(fa1[nxt], a1b + (kk + 1) * 32);
                ldsm_x4(fb0[nxt], b0b + (kk + 1) * 32);
                ldsm_x4(fb1[nxt], b1b + (kk + 1) * 32);
            }
            mma16816(acc[0][0], fa0[cur], fb0[cur][0], fb0[cur][1]);
            mma16816(acc[0][1], fa0[cur], fb0[cur][2], fb0[cur][3]);
            mma16816(acc[0][2], fa0[cur], fb1[cur][0], fb1[cur][1]);
            mma16816(acc[0][3], fa0[cur], fb1[cur][2], fb1[cur][3]);
            mma16816(acc[1][0], fa1[cur], fb0[cur][0], fb0[cur][1]);
            mma16816(acc[1][1], fa1[cur], fb0[cur][2], fb0[cur][3]);
            mma16816(acc[1][2], fa1[cur], fb1[cur][0], fb1[cur][1]);
            mma16816(acc[1][3], fa1[cur], fb1[cur][2], fb1[cur][3]);
        }
    }
    cp_wait<0>();
    __syncthreads();

    // ---- epilogue via shared fp32 [128][72] aliased over stage buffers ----
    float* Gs = (float*)smem;
#pragma unroll
    for (int mi = 0; mi < 2; mi++)
#pragma unroll
        for (int nj = 0; nj < 4; nj++) {
            int r0 = wm * 32 + mi * 16 + g;
            int ncol = wn * 32 + nj * 8 + 2 * tg;
            Gs[r0 * ASTR + ncol]           = acc[mi][nj][0];
            Gs[r0 * ASTR + ncol + 1]       = acc[mi][nj][1];
            Gs[(r0 + 8) * ASTR + ncol]     = acc[mi][nj][2];
            Gs[(r0 + 8) * ASTR + ncol + 1] = acc[mi][nj][3];
        }
    __syncthreads();

    if (mode == 2) {
#pragma unroll
        for (int i = 0; i < 32; i++) {
            int e = tid + i * NTHR;
            int b = e >> 6, n = e & 63;
            out[((long)b * TT + step) * OO + n] = Gs[b * ASTR + n] + b_out[n];
        }
        return;
    }

    const float* bc = (mode == 0) ? d_bc1 : d_bc2;
    float* C        = (mode == 0) ? d_C1 : d_C2;
    __half* Hdst    = ((mode == 0) ? d_H1 : d_H2) + par * (BB * HH);
    const int jbase = n0 >> 2;
#pragma unroll
    for (int i = 0; i < 8; i++) {
        int e = tid + i * NTHR;                  // 2048 quad-units
        int b = e >> 4, uu = e & 15;
        const float* gq = Gs + b * ASTR + 4 * uu;
        float gi = gq[0] + bc[n0 + 4 * uu + 0];
        float gf = gq[1] + bc[n0 + 4 * uu + 1];
        float gg = gq[2] + bc[n0 + 4 * uu + 2];
        float go = gq[3] + bc[n0 + 4 * uu + 3];
        float iv = sigmoidf_(gi);
        float fv = sigmoidf_(gf);
        float gv = tanhf(gg);
        float ov = sigmoidf_(go);
        int j = jbase + uu;
        float cold = C[b * HH + j];
        float cn = fv * cold + iv * gv;
        C[b * HH + j] = cn;
        Hdst[b * HH + j] = __float2half(ov * tanhf(cn));
    }
}

// ---------------- persistent kernel ----------------
// Phase P(t): layer1(t) [bx 0..63] || layer2(t-1) [bx 64..127] || y(t-2) [bx 128]
__global__ __launch_bounds__(NTHR, 1)
void lstm_persistent(const float* __restrict__ b_out, float* __restrict__ out)
{
    extern __shared__ __half smem[];
    const int bx = blockIdx.x;
    unsigned target = 0;

    for (int t = 0; t <= TT + 1; t++) {
        if (bx < 64) {
            if (t < TT) do_tile(0, t, bx * NT, smem, b_out, out);
        } else if (bx < 128) {
            if (t >= 1 && t <= TT) do_tile(1, t - 1, (bx - 64) * NT, smem, b_out, out);
        } else {
            if (t >= 2) do_tile(2, t - 2, 0, smem, b_out, out);
        }
        target += NB;
        grid_barrier(target);
    }
}

// ---------------- launch ----------------
extern "C" void kernel_launch(void* const* d_in, const int* in_sizes, int n_in,
                              void* d_out, int out_size)
{
    const float* x     = (const float*)d_in[0];
    const float* Wih1  = (const float*)d_in[1];
    const float* Whh1  = (const float*)d_in[2];
    const float* bih1  = (const float*)d_in[3];
    const float* bhh1  = (const float*)d_in[4];
    const float* Wih2  = (const float*)d_in[5];
    const float* Whh2  = (const float*)d_in[6];
    const float* bih2  = (const float*)d_in[7];
    const float* bhh2  = (const float*)d_in[8];
    const float* Wout  = (const float*)d_in[9];
    const float* bout  = (const float*)d_in[10];
    float* out = (float*)d_out;

    cudaFuncSetAttribute(lstm_persistent,
                         cudaFuncAttributeMaxDynamicSharedMemorySize, SMEM_BYTES);

    init_kernel<<<1024, 256>>>(x, Wih1, Whh1, bih1, bhh1, Wih2, Whh2, bih2, bhh2, Wout);
    lstm_persistent<<<NB, NTHR, SMEM_BYTES>>>(bout, out);
}

// round 9
// speedup vs baseline: 1.6804x; 1.3536x over previous
#include <cuda_runtime.h>
#include <cuda_fp16.h>
#include <cstdint>

// Problem constants
#define BB   128
#define TT   512
#define HH   1024
#define GG   4096
#define OO   64

#define KC   64            // K per chunk
#define MT   64            // gate rows per block tile (M)
#define AP   72            // padded k-extent of weight tile rows (halfs)
#define BP   136           // padded batch extent of activation rows (halfs)
#define NSTG 4
#define NB   129
#define NTHR 256

#define WTILE_HALFS (MT * AP)          // 4608
#define ATILE_BYTES (WTILE_HALFS * 2)  // 9216
#define BTILE_HALFS (KC * BP)          // 8704
#define BTILE_BYTES (BTILE_HALFS * 2)  // 17408
#define STAGE_BYTES (ATILE_BYTES + BTILE_BYTES)   // 26624
#define SMEM_BYTES  (NSTG * STAGE_BYTES + 64)     // + mbarriers

// ---------------- scratch ----------------
__device__ __align__(128) __half d_Wp1[64 * 17 * WTILE_HALFS];  // layer1 prepacked tiles
__device__ __align__(128) __half d_Wp2[64 * 32 * WTILE_HALFS];  // layer2 prepacked tiles
__device__ __align__(128) __half d_Wpo[16 * WTILE_HALFS];       // y-proj prepacked tiles
__device__ __align__(128) float  d_bc1[GG];
__device__ __align__(128) float  d_bc2[GG];
__device__ __align__(128) __half d_Xt [TT * BTILE_HALFS];       // x transposed [t][k64][b136]
__device__ __align__(128) __half d_H1t[2 * HH * BP];            // h1 [parity][j][b136]
__device__ __align__(128) __half d_H2t[2 * HH * BP];
__device__ __align__(128) float  d_C1 [HH * BB];                // c [j][b]
__device__ __align__(128) float  d_C2 [HH * BB];
__device__ unsigned g_bar;

// ---------------- init: convert + transpose + prepack ----------------
__global__ void init_kernel(const float* __restrict__ x,
                            const float* __restrict__ Wih1, const float* __restrict__ Whh1,
                            const float* __restrict__ bih1, const float* __restrict__ bhh1,
                            const float* __restrict__ Wih2, const float* __restrict__ Whh2,
                            const float* __restrict__ bih2, const float* __restrict__ bhh2,
                            const float* __restrict__ Wout)
{
    long tid = (long)blockIdx.x * blockDim.x + threadIdx.x;
    long stride = (long)gridDim.x * blockDim.x;
    if (tid == 0) g_bar = 0u;

    // Wp1 tiles: [bi][c][mi][kl], m = bi*64+mi = 4j+g, K = [x(64) | h1(1024)]
    for (long idx = tid; idx < (long)64 * 17 * WTILE_HALFS; idx += stride) {
        int tile = (int)(idx / WTILE_HALFS), rem = (int)(idx % WTILE_HALFS);
        int mi = rem / AP, kl = rem % AP;
        int bi = tile / 17, c = tile % 17;
        float v = 0.f;
        if (kl < KC) {
            int m = bi * 64 + mi, j = m >> 2, g = m & 3;
            int sj = g * HH + j;
            int kg = c * KC + kl;
            v = (kg < 64) ? Wih1[(long)sj * 64 + kg] : Whh1[(long)sj * HH + (kg - 64)];
        }
        d_Wp1[idx] = __float2half(v);
    }
    // Wp2 tiles: K = [h1(1024) | h2(1024)]
    for (long idx = tid; idx < (long)64 * 32 * WTILE_HALFS; idx += stride) {
        int tile = (int)(idx / WTILE_HALFS), rem = (int)(idx % WTILE_HALFS);
        int mi = rem / AP, kl = rem % AP;
        int bi = tile / 32, c = tile % 32;
        float v = 0.f;
        if (kl < KC) {
            int m = bi * 64 + mi, j = m >> 2, g = m & 3;
            int sj = g * HH + j;
            int kg = c * KC + kl;
            v = (kg < HH) ? Wih2[(long)sj * HH + kg] : Whh2[(long)sj * HH + (kg - HH)];
        }
        d_Wp2[idx] = __float2half(v);
    }
    // Wpo tiles
    for (long idx = tid; idx < (long)16 * WTILE_HALFS; idx += stride) {
        int c = (int)(idx / WTILE_HALFS), rem = (int)(idx % WTILE_HALFS);
        int mi = rem / AP, kl = rem % AP;
        float v = 0.f;
        if (kl < KC) v = Wout[(long)mi * HH + c * KC + kl];
        d_Wpo[idx] = __float2half(v);
    }
    // biases (gate-interleaved order: row = 4j+g)
    for (long idx = tid; idx < GG; idx += stride) {
        int row = (int)idx, j = row >> 2, g = row & 3;
        int sj = g * HH + j;
        d_bc1[row] = bih1[sj] + bhh1[sj];
        d_bc2[row] = bih2[sj] + bhh2[sj];
    }
    // x transposed: [t][kl][b] padded
    for (long idx = tid; idx < (long)TT * BTILE_HALFS; idx += stride) {
        int t = (int)(idx / BTILE_HALFS), rem = (int)(idx % BTILE_HALFS);
        int kl = rem / BP, b = rem % BP;
        float v = (b < BB) ? x[((long)b * TT + t) * 64 + kl] : 0.f;
        d_Xt[idx] = __float2half(v);
    }
    // zero state
    for (long idx = tid; idx < (long)2 * HH * BP; idx += stride) {
        d_H1t[idx] = __float2half(0.f);
        d_H2t[idx] = __float2half(0.f);
    }
    for (long idx = tid; idx < (long)HH * BB; idx += stride) {
        d_C1[idx] = 0.f;
        d_C2[idx] = 0.f;
    }
}

// ---------------- helpers ----------------
__device__ __forceinline__ void mbar_init(uint32_t mbar, uint32_t count) {
    asm volatile("mbarrier.init.shared.b64 [%0], %1;" :: "r"(mbar), "r"(count) : "memory");
}
__device__ __forceinline__ void mbar_expect_tx(uint32_t mbar, uint32_t bytes) {
    asm volatile("mbarrier.arrive.expect_tx.shared.b64 _, [%0], %1;" :: "r"(mbar), "r"(bytes) : "memory");
}
__device__ __forceinline__ void mbar_wait(uint32_t mbar, uint32_t parity) {
    asm volatile(
        "{\n\t.reg .pred P;\n\t"
        "W_%=:\n\t"
        "mbarrier.try_wait.parity.acquire.cta.shared::cta.b64 P, [%0], %1;\n\t"
        "@!P bra W_%=;\n\t}"
        :: "r"(mbar), "r"(parity) : "memory");
}
__device__ __forceinline__ void bulk_g2s(uint32_t dst, const void* src, uint32_t bytes, uint32_t mbar) {
    asm volatile("cp.async.bulk.shared::cluster.global.mbarrier::complete_tx::bytes [%0], [%1], %2, [%3];"
                 :: "r"(dst), "l"(src), "r"(bytes), "r"(mbar) : "memory");
}
__device__ __forceinline__ void ldsm_x4(uint32_t* r, uint32_t addr) {
    asm volatile("ldmatrix.sync.aligned.m8n8.x4.shared.b16 {%0,%1,%2,%3}, [%4];"
                 : "=r"(r[0]), "=r"(r[1]), "=r"(r[2]), "=r"(r[3]) : "r"(addr));
}
__device__ __forceinline__ void ldsm_x4_t(uint32_t* r, uint32_t addr) {
    asm volatile("ldmatrix.sync.aligned.m8n8.x4.trans.shared.b16 {%0,%1,%2,%3}, [%4];"
                 : "=r"(r[0]), "=r"(r[1]), "=r"(r[2]), "=r"(r[3]) : "r"(addr));
}
__device__ __forceinline__ void mma16816(float* c, const uint32_t* a, uint32_t b0, uint32_t b1) {
    asm volatile(
        "mma.sync.aligned.m16n8k16.row.col.f32.f16.f16.f32 "
        "{%0,%1,%2,%3}, {%4,%5,%6,%7}, {%8,%9}, {%0,%1,%2,%3};\n"
        : "+f"(c[0]), "+f"(c[1]), "+f"(c[2]), "+f"(c[3])
        : "r"(a[0]), "r"(a[1]), "r"(a[2]), "r"(a[3]), "r"(b0), "r"(b1));
}
__device__ __forceinline__ float sigmoidf_(float v) { return 1.f / (1.f + expf(-v)); }

__device__ __forceinline__ void grid_barrier(unsigned target) {
    __threadfence();
    __syncthreads();
    if (threadIdx.x == 0) {
        atomicAdd(&g_bar, 1u);
        while (*(volatile unsigned*)&g_bar < target) { }
    }
    __syncthreads();
    __threadfence();
}

// ---------------- one GEMM tile (D[m=gates][n=batch]) + epilogue ----------------
// mode 0: layer1 gates step t (K=1088: [x_t | h1(t-1)])
// mode 1: layer2 gates step s (K=2048: [h1(s) | h2(s-1)])
// mode 2: y projection step u (K=1024: h2(u))
__device__ void do_tile(int mode, int step, int bi, char* smem,
                        const float* __restrict__ b_out, float* __restrict__ out)
{
    const int tid = threadIdx.x;
    const uint32_t smem_u32 = (uint32_t)__cvta_generic_to_shared(smem);
    const uint32_t mb = smem_u32 + NSTG * STAGE_BYTES;   // 4 mbarriers

    int nc;
    const __half* Wtiles;
    if (mode == 0)      { nc = 17; Wtiles = d_Wp1 + (long)bi * 17 * WTILE_HALFS; }
    else if (mode == 1) { nc = 32; Wtiles = d_Wp2 + (long)bi * 32 * WTILE_HALFS; }
    else                { nc = 16; Wtiles = d_Wpo; }
    const int par = step & 1, parq = par ^ 1;

    // re-init mbarriers (quiescent between tiles)
    if (tid == 0) {
#pragma unroll
        for (int s = 0; s < NSTG; s++) mbar_init(mb + s * 8, 1);
        asm volatile("fence.proxy.async.shared::cta;" ::: "memory");
    }
    __syncthreads();

    auto act_src = [&](int c) -> const __half* {
        if (mode == 0) {
            if (c == 0) return d_Xt + (long)step * BTILE_HALFS;
            return d_H1t + (long)parq * HH * BP + (long)(c - 1) * BTILE_HALFS;
        }
        if (mode == 1) {
            if (c < 16) return d_H1t + (long)par  * HH * BP + (long)c * BTILE_HALFS;
            return d_H2t + (long)parq * HH * BP + (long)(c - 16) * BTILE_HALFS;
        }
        return d_H2t + (long)par * HH * BP + (long)c * BTILE_HALFS;
    };

    auto issue = [&](int c) {
        int slot = c & 3;
        uint32_t st = smem_u32 + slot * STAGE_BYTES;
        mbar_expect_tx(mb + slot * 8, STAGE_BYTES);
        bulk_g2s(st,               Wtiles + (long)c * WTILE_HALFS, ATILE_BYTES, mb + slot * 8);
        bulk_g2s(st + ATILE_BYTES, act_src(c),                     BTILE_BYTES, mb + slot * 8);
    };

    if (tid == 0) { issue(0); issue(1); issue(2); }

    const int warp = tid >> 5, lane = tid & 31;
    const int wm = warp & 1, wn = warp >> 1;        // 2 M-groups x 4 N-groups, warp tile 32x32
    const int g = lane >> 2, tg = lane & 3;
    const int mat = lane >> 3, r8 = lane & 7;

    // ldsm lane offsets (halfs within stage)
    // A (weights [64 m][72 k]) non-trans: x4 covers m16 x k16
    const int a_row = (mat & 1) * 8 + r8, a_col = (mat >> 1) * 8;
    // B (activations [64 k][136 n]) trans: x4 covers k16 x n16
    const int b_krow = (mat & 1) * 8 + r8, b_ncol = (mat >> 1) * 8;

    float acc[2][4][4];
#pragma unroll
    for (int i = 0; i < 2; i++)
#pragma unroll
        for (int j = 0; j < 4; j++)
#pragma unroll
            for (int k = 0; k < 4; k++) acc[i][j][k] = 0.f;

    for (int c = 0; c < nc; c++) {
        __syncthreads();                       // everyone done with compute (c-1) -> slot (c+3)&3 free
        if (tid == 0 && c + 3 < nc) issue(c + 3);
        mbar_wait(mb + (c & 3) * 8, (c >> 2) & 1);

        uint32_t st = smem_u32 + (c & 3) * STAGE_BYTES;
        uint32_t aB = st + 2 * ((wm * 32 + a_row) * AP + a_col);
        uint32_t bB = st + ATILE_BYTES + 2 * (b_krow * BP + (wn * 32 + b_ncol));
#pragma unroll
        for (int kk = 0; kk < 4; kk++) {
            uint32_t fa[2][4], fb[2][4];
            ldsm_x4  (fa[0], aB + 2 * (kk * 16));
            ldsm_x4  (fa[1], aB + 2 * (16 * AP + kk * 16));
            ldsm_x4_t(fb[0], bB + 2 * (kk * 16 * BP));
            ldsm_x4_t(fb[1], bB + 2 * (kk * 16 * BP + 16));
#pragma unroll
            for (int mi = 0; mi < 2; mi++) {
                mma16816(acc[mi][0], fa[mi], fb[0][0], fb[0][1]);
                mma16816(acc[mi][1], fa[mi], fb[0][2], fb[0][3]);
                mma16816(acc[mi][2], fa[mi], fb[1][0], fb[1][1]);
                mma16816(acc[mi][3], fa[mi], fb[1][2], fb[1][3]);
            }
        }
    }
    __syncthreads();

    // ---- stage gates to shared fp32 [64 m][132] (aliases stages 0-1) ----
    float* Gs = (float*)smem;
#pragma unroll
    for (int mi = 0; mi < 2; mi++)
#pragma unroll
        for (int nj = 0; nj < 4; nj++) {
            int m0 = wm * 32 + mi * 16 + g;
            int n0 = wn * 32 + nj * 8 + 2 * tg;
            Gs[m0 * 132 + n0]           = acc[mi][nj][0];
            Gs[m0 * 132 + n0 + 1]       = acc[mi][nj][1];
            Gs[(m0 + 8) * 132 + n0]     = acc[mi][nj][2];
            Gs[(m0 + 8) * 132 + n0 + 1] = acc[mi][nj][3];
        }
    __syncthreads();

    if (mode == 2) {
#pragma unroll
        for (int i = 0; i < 32; i++) {
            int e = tid + i * NTHR;                  // 8192 = 128 b x 64 o
            int b = e >> 6, o = e & 63;
            out[((long)b * TT + step) * OO + o] = Gs[o * 132 + b] + b_out[o];
        }
        return;
    }

    const float* bc = (mode == 0) ? d_bc1 : d_bc2;
    float* C        = (mode == 0) ? d_C1 : d_C2;
    __half* Hdst    = ((mode == 0) ? d_H1t : d_H2t) + (long)par * HH * BP;
    const int m0g   = bi * 64;
#pragma unroll
    for (int i = 0; i < 8; i++) {
        int e = tid + i * NTHR;                      // 2048 = 16 j x 128 b
        int jl = e >> 7, b = e & 127;
        const float* gq = Gs + (4 * jl) * 132 + b;
        float gi = gq[0]       + bc[m0g + 4 * jl + 0];
        float gf = gq[132]     + bc[m0g + 4 * jl + 1];
        float gg = gq[264]     + bc[m0g + 4 * jl + 2];
        float go = gq[396]     + bc[m0g + 4 * jl + 3];
        float iv = sigmoidf_(gi);
        float fv = sigmoidf_(gf);
        float gv = tanhf(gg);
        float ov = sigmoidf_(go);
        int j = bi * 16 + jl;
        float cold = C[j * BB + b];
        float cn = fv * cold + iv * gv;
        C[j * BB + b] = cn;
        Hdst[j * BP + b] = __float2half(ov * tanhf(cn));
    }
}

// ---------------- persistent kernel ----------------
// Phase P(t): layer1(t) [bx 0..63] || layer2(t-1) [bx 64..127] || y(t-2) [bx 128]
__global__ __launch_bounds__(NTHR, 1)
void lstm_persistent(const float* __restrict__ b_out, float* __restrict__ out)
{
    extern __shared__ char smem[];
    const int bx = blockIdx.x;
    unsigned target = 0;

    for (int t = 0; t <= TT + 1; t++) {
        if (bx < 64) {
            if (t < TT) do_tile(0, t, bx, smem, b_out, out);
        } else if (bx < 128) {
            if (t >= 1 && t <= TT) do_tile(1, t - 1, bx - 64, smem, b_out, out);
        } else {
            if (t >= 2) do_tile(2, t - 2, 0, smem, b_out, out);
        }
        target += NB;
        grid_barrier(target);
    }
}

// ---------------- launch ----------------
extern "C" void kernel_launch(void* const* d_in, const int* in_sizes, int n_in,
                              void* d_out, int out_size)
{
    const float* x     = (const float*)d_in[0];
    const float* Wih1  = (const float*)d_in[1];
    const float* Whh1  = (const float*)d_in[2];
    const float* bih1  = (const float*)d_in[3];
    const float* bhh1  = (const float*)d_in[4];
    const float* Wih2  = (const float*)d_in[5];
    const float* Whh2  = (const float*)d_in[6];
    const float* bih2  = (const float*)d_in[7];
    const float* bhh2  = (const float*)d_in[8];
    const float* Wout  = (const float*)d_in[9];
    const float* bout  = (const float*)d_in[10];
    float* out = (float*)d_out;

    cudaFuncSetAttribute(lstm_persistent,
                         cudaFuncAttributeMaxDynamicSharedMemorySize, SMEM_BYTES);

    init_kernel<<<2048, 256>>>(x, Wih1, Whh1, bih1, bhh1, Wih2, Whh2, bih2, bhh2, Wout);
    lstm_persistent<<<NB, NTHR, SMEM_BYTES>>>(bout, out);
}

// round 12
// speedup vs baseline: 2.0024x; 1.1916x over previous
#include <cuda_runtime.h>
#include <cuda_fp16.h>
#include <cstdint>

// Problem constants
#define BB   128
#define TT   512
#define HH   1024
#define GG   4096
#define OO   64

#define KC   64            // K per chunk
#define AP   72            // padded k-extent of weight tile rows (halfs)
#define BP   136           // padded batch extent of activation rows (halfs)
#define NSTG 4
#define NB   129
#define NTHR 288           // 8 compute warps + 1 producer warp

#define WTILE_HALFS (64 * AP)          // 4608
#define ATILE_BYTES (WTILE_HALFS * 2)  // 9216
#define BTILE_HALFS (KC * BP)          // 8704
#define BTILE_BYTES (BTILE_HALFS * 2)  // 17408
#define STAGE_BYTES (ATILE_BYTES + BTILE_BYTES)   // 26624
#define SMEM_BYTES  (NSTG * STAGE_BYTES + 128)    // + mbarriers

// ---------------- scratch ----------------
__device__ __align__(128) __half d_Wp1[64 * 17 * WTILE_HALFS];  // layer1 prepacked tiles
__device__ __align__(128) __half d_Wp2[64 * 32 * WTILE_HALFS];  // layer2 prepacked tiles
__device__ __align__(128) __half d_Wpo[16 * WTILE_HALFS];       // y-proj prepacked tiles
__device__ __align__(128) float  d_bc1[GG];
__device__ __align__(128) float  d_bc2[GG];
__device__ __align__(128) __half d_Xt [TT * BTILE_HALFS];       // x transposed [t][k64][b136]
__device__ __align__(128) __half d_H1t[2 * HH * BP];            // h1 [parity][j][b136]
__device__ __align__(128) __half d_H2t[2 * HH * BP];
__device__ __align__(128) float  d_C1 [HH * BB];                // c [j][b]
__device__ __align__(128) float  d_C2 [HH * BB];
__device__ unsigned g_bar;

// ---------------- init: convert + transpose + prepack ----------------
__global__ void init_kernel(const float* __restrict__ x,
                            const float* __restrict__ Wih1, const float* __restrict__ Whh1,
                            const float* __restrict__ bih1, const float* __restrict__ bhh1,
                            const float* __restrict__ Wih2, const float* __restrict__ Whh2,
                            const float* __restrict__ bih2, const float* __restrict__ bhh2,
                            const float* __restrict__ Wout)
{
    long tid = (long)blockIdx.x * blockDim.x + threadIdx.x;
    long stride = (long)gridDim.x * blockDim.x;
    if (tid == 0) g_bar = 0u;

    // Wp1 tiles: [bi][c][mi][kl], m = bi*64+mi = 4j+g, K = [x(64) | h1(1024)]
    for (long idx = tid; idx < (long)64 * 17 * WTILE_HALFS; idx += stride) {
        int tile = (int)(idx / WTILE_HALFS), rem = (int)(idx % WTILE_HALFS);
        int mi = rem / AP, kl = rem % AP;
        int bi = tile / 17, c = tile % 17;
        float v = 0.f;
        if (kl < KC) {
            int m = bi * 64 + mi, j = m >> 2, g = m & 3;
            int sj = g * HH + j;
            int kg = c * KC + kl;
            v = (kg < 64) ? Wih1[(long)sj * 64 + kg] : Whh1[(long)sj * HH + (kg - 64)];
        }
        d_Wp1[idx] = __float2half(v);
    }
    // Wp2 tiles: K = [h1(1024) | h2(1024)]
    for (long idx = tid; idx < (long)64 * 32 * WTILE_HALFS; idx += stride) {
        int tile = (int)(idx / WTILE_HALFS), rem = (int)(idx % WTILE_HALFS);
        int mi = rem / AP, kl = rem % AP;
        int bi = tile / 32, c = tile % 32;
        float v = 0.f;
        if (kl < KC) {
            int m = bi * 64 + mi, j = m >> 2, g = m & 3;
            int sj = g * HH + j;
            int kg = c * KC + kl;
            v = (kg < HH) ? Wih2[(long)sj * HH + kg] : Whh2[(long)sj * HH + (kg - HH)];
        }
        d_Wp2[idx] = __float2half(v);
    }
    // Wpo tiles
    for (long idx = tid; idx < (long)16 * WTILE_HALFS; idx += stride) {
        int c = (int)(idx / WTILE_HALFS), rem = (int)(idx % WTILE_HALFS);
        int mi = rem / AP, kl = rem % AP;
        float v = 0.f;
        if (kl < KC) v = Wout[(long)mi * HH + c * KC + kl];
        d_Wpo[idx] = __float2half(v);
    }
    // biases (gate-interleaved order: row = 4j+g)
    for (long idx = tid; idx < GG; idx += stride) {
        int row = (int)idx, j = row >> 2, g = row & 3;
        int sj = g * HH + j;
        d_bc1[row] = bih1[sj] + bhh1[sj];
        d_bc2[row] = bih2[sj] + bhh2[sj];
    }
    // x transposed: [t][kl][b] padded
    for (long idx = tid; idx < (long)TT * BTILE_HALFS; idx += stride) {
        int t = (int)(idx / BTILE_HALFS), rem = (int)(idx % BTILE_HALFS);
        int kl = rem / BP, b = rem % BP;
        float v = (b < BB) ? x[((long)b * TT + t) * 64 + kl] : 0.f;
        d_Xt[idx] = __float2half(v);
    }
    // zero state
    for (long idx = tid; idx < (long)2 * HH * BP; idx += stride) {
        d_H1t[idx] = __float2half(0.f);
        d_H2t[idx] = __float2half(0.f);
    }
    for (long idx = tid; idx < (long)HH * BB; idx += stride) {
        d_C1[idx] = 0.f;
        d_C2[idx] = 0.f;
    }
}

// ---------------- helpers ----------------
__device__ __forceinline__ void mbar_init(uint32_t mbar, uint32_t count) {
    asm volatile("mbarrier.init.shared.b64 [%0], %1;" :: "r"(mbar), "r"(count) : "memory");
}
__device__ __forceinline__ void mbar_expect_tx(uint32_t mbar, uint32_t bytes) {
    asm volatile("mbarrier.arrive.expect_tx.shared.b64 _, [%0], %1;" :: "r"(mbar), "r"(bytes) : "memory");
}
__device__ __forceinline__ void mbar_arrive(uint32_t mbar) {
    asm volatile("mbarrier.arrive.shared.b64 _, [%0];" :: "r"(mbar) : "memory");
}
__device__ __forceinline__ void mbar_wait(uint32_t mbar, uint32_t parity) {
    asm volatile(
        "{\n\t.reg .pred P;\n\t"
        "W_%=:\n\t"
        "mbarrier.try_wait.parity.acquire.cta.shared::cta.b64 P, [%0], %1;\n\t"
        "@!P bra W_%=;\n\t}"
        :: "r"(mbar), "r"(parity) : "memory");
}
__device__ __forceinline__ void bulk_g2s(uint32_t dst, const void* src, uint32_t bytes, uint32_t mbar) {
    asm volatile("cp.async.bulk.shared::cluster.global.mbarrier::complete_tx::bytes [%0], [%1], %2, [%3];"
                 :: "r"(dst), "l"(src), "r"(bytes), "r"(mbar) : "memory");
}
__device__ __forceinline__ void ldsm_x4(uint32_t* r, uint32_t addr) {
    asm volatile("ldmatrix.sync.aligned.m8n8.x4.shared.b16 {%0,%1,%2,%3}, [%4];"
                 : "=r"(r[0]), "=r"(r[1]), "=r"(r[2]), "=r"(r[3]) : "r"(addr));
}
__device__ __forceinline__ void ldsm_x4_t(uint32_t* r, uint32_t addr) {
    asm volatile("ldmatrix.sync.aligned.m8n8.x4.trans.shared.b16 {%0,%1,%2,%3}, [%4];"
                 : "=r"(r[0]), "=r"(r[1]), "=r"(r[2]), "=r"(r[3]) : "r"(addr));
}
__device__ __forceinline__ void mma16816(float* c, const uint32_t* a, uint32_t b0, uint32_t b1) {
    asm volatile(
        "mma.sync.aligned.m16n8k16.row.col.f32.f16.f16.f32 "
        "{%0,%1,%2,%3}, {%4,%5,%6,%7}, {%8,%9}, {%0,%1,%2,%3};\n"
        : "+f"(c[0]), "+f"(c[1]), "+f"(c[2]), "+f"(c[3])
        : "r"(a[0]), "r"(a[1]), "r"(a[2]), "r"(a[3]), "r"(b0), "r"(b1));
}
__device__ __forceinline__ float sigmoidf_(float v) { return 1.f / (1.f + expf(-v)); }

__device__ __forceinline__ void grid_barrier(unsigned target) {
    __threadfence();
    __syncthreads();
    if (threadIdx.x == 0) {
        atomicAdd(&g_bar, 1u);
        while (*(volatile unsigned*)&g_bar < target) { }
    }
    __syncthreads();
    __threadfence();
}

// fills/releases of slot s within a tile of nc chunks
__device__ __forceinline__ int qof(int nc, int s) { return (nc + 3 - s) >> 2; }

// ---------------- one GEMM tile (D[m=gates][n=batch]) + epilogue ----------------
// mode 0: layer1 gates step t (K=1088: [x_t | h1(t-1)])
// mode 1: layer2 gates step s (K=2048: [h1(s) | h2(s-1)])
// mode 2: y projection step u (K=1024: h2(u))
__device__ void do_tile(int mode, int step, int bi, int n, char* smem,
                        const float* __restrict__ b_out, float* __restrict__ out)
{
    const int tid = threadIdx.x;
    const int warp = tid >> 5, lane = tid & 31;
    const uint32_t smem_u32 = (uint32_t)__cvta_generic_to_shared(smem);
    const uint32_t MB_F = smem_u32 + NSTG * STAGE_BYTES;      // full barriers (count 1 + tx)
    const uint32_t MB_E = MB_F + 32;                          // empty barriers (count 8)

    int nc;
    const __half* Wtiles;
    if (mode == 0)      { nc = 17; Wtiles = d_Wp1 + (long)bi * 17 * WTILE_HALFS; }
    else if (mode == 1) { nc = 32; Wtiles = d_Wp2 + (long)bi * 32 * WTILE_HALFS; }
    else                { nc = 16; Wtiles = d_Wpo; }
    const int par = step & 1, parq = par ^ 1;

    // ---------------- producer warp ----------------
    if (warp == 8) {
        if (lane == 0) {
            for (int f = 0; f < nc; f++) {
                int s = f & 3;
                if (f >= NSTG)
                    mbar_wait(MB_E + 8 * s, (unsigned)(n * qof(nc, s) + (f >> 2) - 1) & 1);
                uint32_t st = smem_u32 + s * STAGE_BYTES;
                const __half* act;
                if (mode == 0) {
                    act = (f == 0) ? d_Xt + (long)step * BTILE_HALFS
                                   : d_H1t + (long)parq * HH * BP + (long)(f - 1) * BTILE_HALFS;
                } else if (mode == 1) {
                    act = (f < 16) ? d_H1t + (long)par  * HH * BP + (long)f * BTILE_HALFS
                                   : d_H2t + (long)parq * HH * BP + (long)(f - 16) * BTILE_HALFS;
                } else {
                    act = d_H2t + (long)par * HH * BP + (long)f * BTILE_HALFS;
                }
                mbar_expect_tx(MB_F + 8 * s, STAGE_BYTES);
                bulk_g2s(st,               Wtiles + (long)f * WTILE_HALFS, ATILE_BYTES, MB_F + 8 * s);
                bulk_g2s(st + ATILE_BYTES, act,                            BTILE_BYTES, MB_F + 8 * s);
            }
        }
    }

    // ---------------- compute warps ----------------
    const int wm = warp & 1, wn = warp >> 1;        // 2 M-groups x 4 N-groups, warp tile 32x32
    const int g = lane >> 2, tg = lane & 3;
    const int mat = lane >> 3, r8 = lane & 7;

    // ldsm lane offsets (halfs within stage)
    const int aoff = (wm * 32 + (mat & 1) * 8 + r8) * AP + (mat >> 1) * 8;   // A non-trans, m16 x k16
    const int boff = ((mat & 1) * 8 + r8) * BP + wn * 32 + (mat >> 1) * 8;   // B trans, k16 x n16

    float acc[2][4][4];
#pragma unroll
    for (int i = 0; i < 2; i++)
#pragma unroll
        for (int j = 0; j < 4; j++)
#pragma unroll
            for (int k = 0; k < 4; k++) acc[i][j][k] = 0.f;

    if (warp < 8) {
        for (int c = 0; c < nc; c++) {
            int s = c & 3;
            mbar_wait(MB_F + 8 * s, (unsigned)(n * qof(nc, s) + (c >> 2)) & 1);

            uint32_t st = smem_u32 + s * STAGE_BYTES;
            uint32_t aB = st + 2 * aoff;
            uint32_t bB = st + ATILE_BYTES + 2 * boff;

            uint32_t fa[2][2][4], fb[2][2][4];
            ldsm_x4  (fa[0][0], aB);
            ldsm_x4  (fa[0][1], aB + 2 * (16 * AP));
            ldsm_x4_t(fb[0][0], bB);
            ldsm_x4_t(fb[0][1], bB + 2 * 16);
#pragma unroll
            for (int kk = 0; kk < 4; kk++) {
                int cur = kk & 1, nxt = cur ^ 1;
                if (kk < 3) {
                    ldsm_x4  (fa[nxt][0], aB + 2 * ((kk + 1) * 16));
                    ldsm_x4  (fa[nxt][1], aB + 2 * (16 * AP + (kk + 1) * 16));
                    ldsm_x4_t(fb[nxt][0], bB + 2 * ((kk + 1) * 16 * BP));
                    ldsm_x4_t(fb[nxt][1], bB + 2 * ((kk + 1) * 16 * BP + 16));
                }
#pragma unroll
                for (int mi = 0; mi < 2; mi++) {
                    mma16816(acc[mi][0], fa[cur][mi], fb[cur][0][0], fb[cur][0][1]);
                    mma16816(acc[mi][1], fa[cur][mi], fb[cur][0][2], fb[cur][0][3]);
                    mma16816(acc[mi][2], fa[cur][mi], fb[cur][1][0], fb[cur][1][1]);
                    mma16816(acc[mi][3], fa[cur][mi], fb[cur][1][2], fb[cur][1][3]);
                }
            }
            if (lane == 0) mbar_arrive(MB_E + 8 * s);
        }
    }
    __syncthreads();   // all slots drained; safe to alias stage smem

    // ---- stage gates to shared fp32 [64 m][132] (aliases stages 0-2) ----
    float* Gs = (float*)smem;
    if (warp < 8) {
#pragma unroll
        for (int mi = 0; mi < 2; mi++)
#pragma unroll
            for (int nj = 0; nj < 4; nj++) {
                int m0 = wm * 32 + mi * 16 + g;
                int n0 = wn * 32 + nj * 8 + 2 * tg;
                Gs[m0 * 132 + n0]           = acc[mi][nj][0];
                Gs[m0 * 132 + n0 + 1]       = acc[mi][nj][1];
                Gs[(m0 + 8) * 132 + n0]     = acc[mi][nj][2];
                Gs[(m0 + 8) * 132 + n0 + 1] = acc[mi][nj][3];
            }
    }
    __syncthreads();

    if (mode == 2) {
        if (tid < 256) {
#pragma unroll
            for (int i = 0; i < 32; i++) {
                int e = tid + i * 256;                   // 8192 = 128 b x 64 o
                int b = e >> 6, o = e & 63;
                out[((long)b * TT + step) * OO + o] = Gs[o * 132 + b] + b_out[o];
            }
        }
        return;
    }

    if (tid < 256) {
        const float* bc = (mode == 0) ? d_bc1 : d_bc2;
        float* C        = (mode == 0) ? d_C1 : d_C2;
        __half* Hdst    = ((mode == 0) ? d_H1t : d_H2t) + (long)par * HH * BP;
        const int m0g   = bi * 64;
#pragma unroll
        for (int i = 0; i < 8; i++) {
            int e = tid + i * 256;                       // 2048 = 16 j x 128 b
            int jl = e >> 7, b = e & 127;
            const float* gq = Gs + (4 * jl) * 132 + b;
            float gi = gq[0]   + bc[m0g + 4 * jl + 0];
            float gf = gq[132] + bc[m0g + 4 * jl + 1];
            float gg = gq[264] + bc[m0g + 4 * jl + 2];
            float go = gq[396] + bc[m0g + 4 * jl + 3];
            float iv = sigmoidf_(gi);
            float fv = sigmoidf_(gf);
            float gv = tanhf(gg);
            float ov = sigmoidf_(go);
            int j = bi * 16 + jl;
            float cold = C[j * BB + b];
            float cn = fv * cold + iv * gv;
            C[j * BB + b] = cn;
            Hdst[j * BP + b] = __float2half(ov * tanhf(cn));
        }
    }
}

// ---------------- persistent kernel ----------------
// Phase P(t): layer1(t) [bx 0..63] || layer2(t-1) [bx 64..127] || y(t-2) [bx 128]
__global__ __launch_bounds__(NTHR, 1)
void lstm_persistent(const float* __restrict__ b_out, float* __restrict__ out)
{
    extern __shared__ char smem[];
    const int tid = threadIdx.x;
    const uint32_t smem_u32 = (uint32_t)__cvta_generic_to_shared(smem);
    const uint32_t MB_F = smem_u32 + NSTG * STAGE_BYTES;
    const uint32_t MB_E = MB_F + 32;

    if (tid == 0) {
#pragma unroll
        for (int s = 0; s < NSTG; s++) {
            mbar_init(MB_F + 8 * s, 1);
            mbar_init(MB_E + 8 * s, 8);
        }
        asm volatile("fence.proxy.async.shared::cta;" ::: "memory");
    }
    __syncthreads();

    const int bx = blockIdx.x;
    unsigned target = 0;
    int n = 0;

    for (int t = 0; t <= TT + 1; t++) {
        if (bx < 64) {
            if (t < TT) { do_tile(0, t, bx, n, smem, b_out, out); n++; }
        } else if (bx < 128) {
            if (t >= 1 && t <= TT) { do_tile(1, t - 1, bx - 64, n, smem, b_out, out); n++; }
        } else {
            if (t >= 2) { do_tile(2, t - 2, 0, n, smem, b_out, out); n++; }
        }
        target += NB;
        grid_barrier(target);
    }
}

// ---------------- launch ----------------
extern "C" void kernel_launch(void* const* d_in, const int* in_sizes, int n_in,
                              void* d_out, int out_size)
{
    const float* x     = (const float*)d_in[0];
    const float* Wih1  = (const float*)d_in[1];
    const float* Whh1  = (const float*)d_in[2];
    const float* bih1  = (const float*)d_in[3];
    const float* bhh1  = (const float*)d_in[4];
    const float* Wih2  = (const float*)d_in[5];
    const float* Whh2  = (const float*)d_in[6];
    const float* bih2  = (const float*)d_in[7];
    const float* bhh2  = (const float*)d_in[8];
    const float* Wout  = (const float*)d_in[9];
    const float* bout  = (const float*)d_in[10];
    float* out = (float*)d_out;

    cudaFuncSetAttribute(lstm_persistent,
                         cudaFuncAttributeMaxDynamicSharedMemorySize, SMEM_BYTES);

    init_kernel<<<2048, 256>>>(x, Wih1, Whh1, bih1, bhh1, Wih2, Whh2, bih2, bhh2, Wout);
    lstm_persistent<<<NB, NTHR, SMEM_BYTES>>>(bout, out);
}

// round 13
// speedup vs baseline: 2.0287x; 1.0132x over previous
#include <cuda_runtime.h>
#include <cuda_fp16.h>
#include <cstdint>

// Problem constants
#define BB   128
#define TT   512
#define HH   1024
#define GG   4096
#define OO   64

#define KC   128           // K per chunk
#define KAP  136           // weight tile padded k extent (halfs)
#define BP   136           // activation padded batch extent (halfs)
#define NSTG 3
#define NB   129
#define NTHR 288           // 8 compute warps + 1 producer warp

#define WT_HALFS    (64 * KAP)          // 8704
#define ATILE_BYTES (WT_HALFS * 2)      // 17408
#define BTILE_HALFS (KC * BP)           // 17408
#define BTILE_BYTES (BTILE_HALFS * 2)   // 34816
#define BHALF_BYTES (BTILE_BYTES / 2)   // 17408 (64-row half tile)
#define STAGE_BYTES (ATILE_BYTES + BTILE_BYTES)  // 52224
#define SMEM_BYTES  (NSTG * STAGE_BYTES + 128)

#define XT_HALFS (64 * BP)              // 8704 (per-t x tile)
#define GS2      (64 * 132)             // second gate buffer offset (floats)

// ---------------- scratch ----------------
__device__ __align__(128) __half d_Wp1[64 * 9  * WT_HALFS];   // L1 tiles (nc=9, zero-padded tail)
__device__ __align__(128) __half d_Wp2[64 * 16 * WT_HALFS];   // L2 tiles (nc=16)
__device__ __align__(128) __half d_Wpo[      8 * WT_HALFS];   // y tiles  (nc=8)
__device__ __align__(128) float  d_bc1[GG];
__device__ __align__(128) float  d_bc2[GG];
__device__ __align__(128) __half d_Xt [TT * XT_HALFS];        // [t][k64][b136]
__device__ __align__(128) __half d_H1t[2 * HH * BP + 64 * BP];// [parity][j][b136] + overrun slack
__device__ __align__(128) __half d_H2t[2 * HH * BP + 64 * BP];
__device__ __align__(128) float  d_C1 [HH * BB];              // c [j][b]
__device__ __align__(128) float  d_C2 [HH * BB];
__device__ unsigned g_bar;

// ---------------- init: convert + transpose + prepack ----------------
__global__ void init_kernel(const float* __restrict__ x,
                            const float* __restrict__ Wih1, const float* __restrict__ Whh1,
                            const float* __restrict__ bih1, const float* __restrict__ bhh1,
                            const float* __restrict__ Wih2, const float* __restrict__ Whh2,
                            const float* __restrict__ bih2, const float* __restrict__ bhh2,
                            const float* __restrict__ Wout)
{
    long tid = (long)blockIdx.x * blockDim.x + threadIdx.x;
    long stride = (long)gridDim.x * blockDim.x;
    if (tid == 0) g_bar = 0u;

    // L1 tiles: [bi][c][mi][kl], m = bi*64+mi = 4j+g, K = [x(64) | h1(1024)] padded to 1152
    for (long idx = tid; idx < (long)64 * 9 * WT_HALFS; idx += stride) {
        int tile = (int)(idx / WT_HALFS), rem = (int)(idx % WT_HALFS);
        int mi = rem / KAP, kl = rem % KAP;
        int bi = tile / 9, c = tile % 9;
        float v = 0.f;
        if (kl < KC) {
            int kg = c * KC + kl;
            int m = bi * 64 + mi, j = m >> 2, g = m & 3;
            int sj = g * HH + j;
            if (kg < 64)        v = Wih1[(long)sj * 64 + kg];
            else if (kg < 1088) v = Whh1[(long)sj * HH + (kg - 64)];
        }
        d_Wp1[idx] = __float2half(v);
    }
    // L2 tiles: K = [h1(1024) | h2(1024)]
    for (long idx = tid; idx < (long)64 * 16 * WT_HALFS; idx += stride) {
        int tile = (int)(idx / WT_HALFS), rem = (int)(idx % WT_HALFS);
        int mi = rem / KAP, kl = rem % KAP;
        int bi = tile / 16, c = tile % 16;
        float v = 0.f;
        if (kl < KC) {
            int kg = c * KC + kl;
            int m = bi * 64 + mi, j = m >> 2, g = m & 3;
            int sj = g * HH + j;
            v = (kg < HH) ? Wih2[(long)sj * HH + kg] : Whh2[(long)sj * HH + (kg - HH)];
        }
        d_Wp2[idx] = __float2half(v);
    }
    // y tiles
    for (long idx = tid; idx < (long)8 * WT_HALFS; idx += stride) {
        int c = (int)(idx / WT_HALFS), rem = (int)(idx % WT_HALFS);
        int mi = rem / KAP, kl = rem % KAP;
        float v = 0.f;
        if (kl < KC) v = Wout[(long)mi * HH + c * KC + kl];
        d_Wpo[idx] = __float2half(v);
    }
    // biases (gate-interleaved: row = 4j+g)
    for (long idx = tid; idx < GG; idx += stride) {
        int row = (int)idx, j = row >> 2, g = row & 3;
        int sj = g * HH + j;
        d_bc1[row] = bih1[sj] + bhh1[sj];
        d_bc2[row] = bih2[sj] + bhh2[sj];
    }
    // x transposed: [t][kl][b] padded
    for (long idx = tid; idx < (long)TT * XT_HALFS; idx += stride) {
        int t = (int)(idx / XT_HALFS), rem = (int)(idx % XT_HALFS);
        int kl = rem / BP, b = rem % BP;
        float v = (b < BB) ? x[((long)b * TT + t) * 64 + kl] : 0.f;
        d_Xt[idx] = __float2half(v);
    }
    // zero state (incl. slack)
    for (long idx = tid; idx < (long)2 * HH * BP + 64 * BP; idx += stride) {
        d_H1t[idx] = __float2half(0.f);
        d_H2t[idx] = __float2half(0.f);
    }
    for (long idx = tid; idx < (long)HH * BB; idx += stride) {
        d_C1[idx] = 0.f;
        d_C2[idx] = 0.f;
    }
}

// ---------------- helpers ----------------
__device__ __forceinline__ void mbar_init(uint32_t mbar, uint32_t count) {
    asm volatile("mbarrier.init.shared.b64 [%0], %1;" :: "r"(mbar), "r"(count) : "memory");
}
__device__ __forceinline__ void mbar_expect_tx(uint32_t mbar, uint32_t bytes) {
    asm volatile("mbarrier.arrive.expect_tx.shared.b64 _, [%0], %1;" :: "r"(mbar), "r"(bytes) : "memory");
}
__device__ __forceinline__ void mbar_arrive(uint32_t mbar) {
    asm volatile("mbarrier.arrive.shared.b64 _, [%0];" :: "r"(mbar) : "memory");
}
__device__ __forceinline__ void mbar_wait(uint32_t mbar, uint32_t parity) {
    asm volatile(
        "{\n\t.reg .pred P;\n\t"
        "W_%=:\n\t"
        "mbarrier.try_wait.parity.acquire.cta.shared::cta.b64 P, [%0], %1;\n\t"
        "@!P bra W_%=;\n\t}"
        :: "r"(mbar), "r"(parity) : "memory");
}
__device__ __forceinline__ void bulk_g2s(uint32_t dst, const void* src, uint32_t bytes, uint32_t mbar) {
    asm volatile("cp.async.bulk.shared::cluster.global.mbarrier::complete_tx::bytes [%0], [%1], %2, [%3];"
                 :: "r"(dst), "l"(src), "r"(bytes), "r"(mbar) : "memory");
}
__device__ __forceinline__ void ldsm_x4(uint32_t* r, uint32_t addr) {
    asm volatile("ldmatrix.sync.aligned.m8n8.x4.shared.b16 {%0,%1,%2,%3}, [%4];"
                 : "=r"(r[0]), "=r"(r[1]), "=r"(r[2]), "=r"(r[3]) : "r"(addr));
}
__device__ __forceinline__ void ldsm_x4_t(uint32_t* r, uint32_t addr) {
    asm volatile("ldmatrix.sync.aligned.m8n8.x4.trans.shared.b16 {%0,%1,%2,%3}, [%4];"
                 : "=r"(r[0]), "=r"(r[1]), "=r"(r[2]), "=r"(r[3]) : "r"(addr));
}
__device__ __forceinline__ void mma16816(float* c, const uint32_t* a, uint32_t b0, uint32_t b1) {
    asm volatile(
        "mma.sync.aligned.m16n8k16.row.col.f32.f16.f16.f32 "
        "{%0,%1,%2,%3}, {%4,%5,%6,%7}, {%8,%9}, {%0,%1,%2,%3};\n"
        : "+f"(c[0]), "+f"(c[1]), "+f"(c[2]), "+f"(c[3])
        : "r"(a[0]), "r"(a[1]), "r"(a[2]), "r"(a[3]), "r"(b0), "r"(b1));
}
__device__ __forceinline__ float sigmoidf_(float v) { return 1.f / (1.f + expf(-v)); }

__device__ __forceinline__ void grid_barrier(unsigned target) {
    __threadfence();
    __syncthreads();
    if (threadIdx.x == 0) {
        atomicAdd(&g_bar, 1u);
        while (*(volatile unsigned*)&g_bar < target) { }
    }
    __syncthreads();
    __threadfence();
}

// ---------------- one GEMM tile (D[m=gates 64][n=batch 128]) + epilogue ----------------
// mode 0: L1 gates step t (nc=9, K=[x|h1(t-1)] padded)
// mode 1: L2 gates step s (nc=16, K=[h1(s)|h2(s-1)])
// mode 2: y proj step u   (nc=8,  K=h2(u))
__device__ __forceinline__ void do_tile(int mode, int step, int bi, char* smem,
        const float* __restrict__ b_out, float* __restrict__ out,
        int& cslot, unsigned& cc0, unsigned& cc1, unsigned& cc2,
        int& pslot, unsigned& pp0, unsigned& pp1, unsigned& pp2)
{
    const int tid = threadIdx.x;
    const int warp = tid >> 5, lane = tid & 31;
    const uint32_t smem_u32 = (uint32_t)__cvta_generic_to_shared(smem);
    const uint32_t MB_F = smem_u32 + NSTG * STAGE_BYTES;   // full barriers (tx)
    const uint32_t MB_E = MB_F + 32;                       // empty barriers (count 8)

    const int nc = (mode == 0) ? 9 : (mode == 1) ? 16 : 8;
    const int par = step & 1, parq = par ^ 1;
    const __half* Wt = (mode == 0) ? d_Wp1 + (long)bi * 9 * WT_HALFS
                     : (mode == 1) ? d_Wp2 + (long)bi * 16 * WT_HALFS
                                   : d_Wpo;

    // ---------------- producer ----------------
    if (warp == 8) {
        if (lane == 0) {
            for (int f = 0; f < nc; f++) {
                if (pp0 >= 1) mbar_wait(MB_E + 8 * pslot, (pp0 - 1) & 1);
                uint32_t st = smem_u32 + pslot * STAGE_BYTES;
                uint32_t bar = MB_F + 8 * pslot;
                mbar_expect_tx(bar, STAGE_BYTES);
                bulk_g2s(st, Wt + (long)f * WT_HALFS, ATILE_BYTES, bar);
                if (mode == 0) {
                    if (f == 0) {
                        bulk_g2s(st + ATILE_BYTES, d_Xt + (long)step * XT_HALFS, BHALF_BYTES, bar);
                        bulk_g2s(st + ATILE_BYTES + BHALF_BYTES,
                                 d_H1t + (long)parq * HH * BP, BHALF_BYTES, bar);
                    } else {
                        bulk_g2s(st + ATILE_BYTES,
                                 d_H1t + (long)parq * HH * BP + ((long)f * KC - 64) * BP,
                                 BTILE_BYTES, bar);
                    }
                } else if (mode == 1) {
                    const __half* act = (f < 8)
                        ? d_H1t + (long)par  * HH * BP + (long)f * KC * BP
                        : d_H2t + (long)parq * HH * BP + (long)(f - 8) * KC * BP;
                    bulk_g2s(st + ATILE_BYTES, act, BTILE_BYTES, bar);
                } else {
                    bulk_g2s(st + ATILE_BYTES,
                             d_H2t + (long)par * HH * BP + (long)f * KC * BP, BTILE_BYTES, bar);
                }
                unsigned t_ = pp0 + 1; pp0 = pp1; pp1 = pp2; pp2 = t_;
                pslot = (pslot == 2) ? 0 : pslot + 1;
            }
        }
    }

    // ---------------- compute warps: 2M x 2N x 2K, warp tile 32x64 ----------------
    const int wk = warp & 1;
    const int wm = (warp >> 1) & 1, wn = warp >> 2;     // wn in {0,1}
    const int g = lane >> 2, tg = lane & 3;
    const int mat = lane >> 3, r8 = lane & 7;

    // lane base offsets (halfs within stage); wk selects kk range [4wk, 4wk+4)
    const int aoff = (wm * 32 + (mat & 1) * 8 + r8) * KAP + (mat >> 1) * 8 + wk * 64;
    const int boff = (wk * 64 + (mat & 1) * 8 + r8) * BP + wn * 64 + (mat >> 1) * 8;

    float acc[2][8][4];
#pragma unroll
    for (int i = 0; i < 2; i++)
#pragma unroll
        for (int j = 0; j < 8; j++)
#pragma unroll
            for (int k = 0; k < 4; k++) acc[i][j][k] = 0.f;

    if (warp < 8) {
        for (int c = 0; c < nc; c++) {
            mbar_wait(MB_F + 8 * cslot, cc0 & 1);
            uint32_t st = smem_u32 + cslot * STAGE_BYTES;
            uint32_t aB = st + 2 * aoff;
            uint32_t bB = st + ATILE_BYTES + 2 * boff;

            uint32_t fa[2][2][4], fb[2][4][4];
            ldsm_x4(fa[0][0], aB);
            ldsm_x4(fa[0][1], aB + 2 * (16 * KAP));
#pragma unroll
            for (int q = 0; q < 4; q++) ldsm_x4_t(fb[0][q], bB + 2 * (16 * q));
#pragma unroll
            for (int kk = 0; kk < 4; kk++) {
                int cur = kk & 1, nxt = cur ^ 1;
                if (kk < 3) {
                    uint32_t aN = aB + 2 * ((kk + 1) * 16);
                    uint32_t bN = bB + 2 * ((kk + 1) * 16 * BP);
                    ldsm_x4(fa[nxt][0], aN);
                    ldsm_x4(fa[nxt][1], aN + 2 * (16 * KAP));
#pragma unroll
                    for (int q = 0; q < 4; q++) ldsm_x4_t(fb[nxt][q], bN + 2 * (16 * q));
                }
#pragma unroll
                for (int mi = 0; mi < 2; mi++)
#pragma unroll
                    for (int q = 0; q < 4; q++) {
                        mma16816(acc[mi][2 * q],     fa[cur][mi], fb[cur][q][0], fb[cur][q][1]);
                        mma16816(acc[mi][2 * q + 1], fa[cur][mi], fb[cur][q][2], fb[cur][q][3]);
                    }
            }
            if (lane == 0) mbar_arrive(MB_E + 8 * cslot);
            unsigned t_ = cc0 + 1; cc0 = cc1; cc1 = cc2; cc2 = t_;
            cslot = (cslot == 2) ? 0 : cslot + 1;
        }
    }
    __syncthreads();   // all slots drained; safe to alias stage smem

    // ---- stage gates to dual fp32 buffers [64 m][132] (K-halves separate) ----
    float* Gs = (float*)smem;
    if (warp < 8) {
        float* G = Gs + wk * GS2;
#pragma unroll
        for (int mi = 0; mi < 2; mi++)
#pragma unroll
            for (int nj = 0; nj < 8; nj++) {
                int m0 = wm * 32 + mi * 16 + g;
                int n0 = wn * 64 + nj * 8 + 2 * tg;
                G[m0 * 132 + n0]           = acc[mi][nj][0];
                G[m0 * 132 + n0 + 1]       = acc[mi][nj][1];
                G[(m0 + 8) * 132 + n0]     = acc[mi][nj][2];
                G[(m0 + 8) * 132 + n0 + 1] = acc[mi][nj][3];
            }
    }
    __syncthreads();

    if (mode == 2) {
        if (tid < 256) {
#pragma unroll
            for (int i = 0; i < 32; i++) {
                int e = tid + i * 256;                   // 8192 = 128 b x 64 o
                int b = e >> 6, o = e & 63;
                out[((long)b * TT + step) * OO + o] =
                    Gs[o * 132 + b] + Gs[GS2 + o * 132 + b] + b_out[o];
            }
        }
        return;
    }

    if (tid < 256) {
        const float* bc = (mode == 0) ? d_bc1 : d_bc2;
        float* C        = (mode == 0) ? d_C1 : d_C2;
        __half* Hdst    = ((mode == 0) ? d_H1t : d_H2t) + (long)par * HH * BP;
        const int m0g   = bi * 64;
#pragma unroll
        for (int i = 0; i < 8; i++) {
            int e = tid + i * 256;                       // 2048 = 16 j x 128 b
            int jl = e >> 7, b = e & 127;
            const float* gq = Gs + (4 * jl) * 132 + b;
            float gi = gq[0]   + gq[GS2]       + bc[m0g + 4 * jl + 0];
            float gf = gq[132] + gq[GS2 + 132] + bc[m0g + 4 * jl + 1];
            float gg = gq[264] + gq[GS2 + 264] + bc[m0g + 4 * jl + 2];
            float go = gq[396] + gq[GS2 + 396] + bc[m0g + 4 * jl + 3];
            float iv = sigmoidf_(gi);
            float fv = sigmoidf_(gf);
            float gv = tanhf(gg);
            float ov = sigmoidf_(go);
            int j = bi * 16 + jl;
            float cold = C[j * BB + b];
            float cn = fv * cold + iv * gv;
            C[j * BB + b] = cn;
            Hdst[j * BP + b] = __float2half(ov * tanhf(cn));
        }
    }
}

// ---------------- persistent kernel ----------------
// Phase P(t): L1(t) [bx 0..63] || L2(t-1) [bx 64..127] || y(t-2) [bx 128]
__global__ __launch_bounds__(NTHR, 1)
void lstm_persistent(const float* __restrict__ b_out, float* __restrict__ out)
{
    extern __shared__ char smem[];
    const int tid = threadIdx.x;
    const uint32_t smem_u32 = (uint32_t)__cvta_generic_to_shared(smem);
    const uint32_t MB_F = smem_u32 + NSTG * STAGE_BYTES;
    const uint32_t MB_E = MB_F + 32;

    if (tid == 0) {
#pragma unroll
        for (int s = 0; s < NSTG; s++) {
            mbar_init(MB_F + 8 * s, 1);
            mbar_init(MB_E + 8 * s, 8);
        }
        asm volatile("fence.proxy.async.shared::cta;" ::: "memory");
    }
    __syncthreads();

    const int bx = blockIdx.x;
    unsigned target = 0;
    int cslot = 0, pslot = 0;
    unsigned cc0 = 0, cc1 = 0, cc2 = 0, pp0 = 0, pp1 = 0, pp2 = 0;

    for (int t = 0; t <= TT + 1; t++) {
        if (bx < 64) {
            if (t < TT)
                do_tile(0, t, bx, smem, b_out, out, cslot, cc0, cc1, cc2, pslot, pp0, pp1, pp2);
        } else if (bx < 128) {
            if (t >= 1 && t <= TT)
                do_tile(1, t - 1, bx - 64, smem, b_out, out, cslot, cc0, cc1, cc2, pslot, pp0, pp1, pp2);
        } else {
            if (t >= 2)
                do_tile(2, t - 2, 0, smem, b_out, out, cslot, cc0, cc1, cc2, pslot, pp0, pp1, pp2);
        }
        target += NB;
        grid_barrier(target);
    }
}

// ---------------- launch ----------------
extern "C" void kernel_launch(void* const* d_in, const int* in_sizes, int n_in,
                              void* d_out, int out_size)
{
    const float* x     = (const float*)d_in[0];
    const float* Wih1  = (const float*)d_in[1];
    const float* Whh1  = (const float*)d_in[2];
    const float* bih1  = (const float*)d_in[3];
    const float* bhh1  = (const float*)d_in[4];
    const float* Wih2  = (const float*)d_in[5];
    const float* Whh2  = (const float*)d_in[6];
    const float* bih2  = (const float*)d_in[7];
    const float* bhh2  = (const float*)d_in[8];
    const float* Wout  = (const float*)d_in[9];
    const float* bout  = (const float*)d_in[10];
    float* out = (float*)d_out;

    cudaFuncSetAttribute(lstm_persistent,
                         cudaFuncAttributeMaxDynamicSharedMemorySize, SMEM_BYTES);

    init_kernel<<<2048, 256>>>(x, Wih1, Whh1, bih1, bhh1, Wih2, Whh2, bih2, bhh2, Wout);
    lstm_persistent<<<NB, NTHR, SMEM_BYTES>>>(bout, out);
}

// round 14
// speedup vs baseline: 2.1312x; 1.0505x over previous
#include <cuda_runtime.h>
#include <cuda_fp16.h>
#include <cstdint>

// Problem constants
#define BB   128
#define TT   512
#define HH   1024
#define GG   4096
#define OO   64

#define KC   128           // K per chunk
#define KAP  136           // weight tile padded k extent (halfs)
#define BP   136           // activation padded batch extent (halfs)
#define NSTG 3
#define NB   129
#define NTHR 544           // 16 compute warps + 1 producer warp

#define WT_HALFS    (64 * KAP)          // 8704
#define ATILE_BYTES (WT_HALFS * 2)      // 17408
#define BTILE_HALFS (KC * BP)           // 17408
#define BTILE_BYTES (BTILE_HALFS * 2)   // 34816
#define BHALF_BYTES (BTILE_BYTES / 2)   // 17408 (64-row half tile)
#define STAGE_BYTES (ATILE_BYTES + BTILE_BYTES)  // 52224
#define SMEM_BYTES  (NSTG * STAGE_BYTES + 128)

#define XT_HALFS (64 * BP)              // 8704 (per-t x tile)
#define GSB      (64 * 132)             // gate staging buffer stride (floats)

// ---------------- scratch ----------------
__device__ __align__(128) __half d_Wp1[64 * 9  * WT_HALFS];   // L1 tiles (nc=9, zero-padded tail)
__device__ __align__(128) __half d_Wp2[64 * 16 * WT_HALFS];   // L2 tiles (nc=16)
__device__ __align__(128) __half d_Wpo[      8 * WT_HALFS];   // y tiles  (nc=8)
__device__ __align__(128) float  d_bc1[GG];
__device__ __align__(128) float  d_bc2[GG];
__device__ __align__(128) __half d_Xt [TT * XT_HALFS];        // [t][k64][b136]
__device__ __align__(128) __half d_H1t[2 * HH * BP + 64 * BP];// [parity][j][b136] + overrun slack
__device__ __align__(128) __half d_H2t[2 * HH * BP + 64 * BP];
__device__ __align__(128) float  d_C1 [HH * BB];              // c [j][b]
__device__ __align__(128) float  d_C2 [HH * BB];
__device__ unsigned g_bar;

// ---------------- init: convert + transpose + prepack ----------------
__global__ void init_kernel(const float* __restrict__ x,
                            const float* __restrict__ Wih1, const float* __restrict__ Whh1,
                            const float* __restrict__ bih1, const float* __restrict__ bhh1,
                            const float* __restrict__ Wih2, const float* __restrict__ Whh2,
                            const float* __restrict__ bih2, const float* __restrict__ bhh2,
                            const float* __restrict__ Wout)
{
    long tid = (long)blockIdx.x * blockDim.x + threadIdx.x;
    long stride = (long)gridDim.x * blockDim.x;
    if (tid == 0) g_bar = 0u;

    // L1 tiles: [bi][c][mi][kl], m = bi*64+mi = 4j+g, K = [x(64) | h1(1024)] padded to 1152
    for (long idx = tid; idx < (long)64 * 9 * WT_HALFS; idx += stride) {
        int tile = (int)(idx / WT_HALFS), rem = (int)(idx % WT_HALFS);
        int mi = rem / KAP, kl = rem % KAP;
        int bi = tile / 9, c = tile % 9;
        float v = 0.f;
        if (kl < KC) {
            int kg = c * KC + kl;
            int m = bi * 64 + mi, j = m >> 2, g = m & 3;
            int sj = g * HH + j;
            if (kg < 64)        v = Wih1[(long)sj * 64 + kg];
            else if (kg < 1088) v = Whh1[(long)sj * HH + (kg - 64)];
        }
        d_Wp1[idx] = __float2half(v);
    }
    // L2 tiles: K = [h1(1024) | h2(1024)]
    for (long idx = tid; idx < (long)64 * 16 * WT_HALFS; idx += stride) {
        int tile = (int)(idx / WT_HALFS), rem = (int)(idx % WT_HALFS);
        int mi = rem / KAP, kl = rem % KAP;
        int bi = tile / 16, c = tile % 16;
        float v = 0.f;
        if (kl < KC) {
            int kg = c * KC + kl;
            int m = bi * 64 + mi, j = m >> 2, g = m & 3;
            int sj = g * HH + j;
            v = (kg < HH) ? Wih2[(long)sj * HH + kg] : Whh2[(long)sj * HH + (kg - HH)];
        }
        d_Wp2[idx] = __float2half(v);
    }
    // y tiles
    for (long idx = tid; idx < (long)8 * WT_HALFS; idx += stride) {
        int c = (int)(idx / WT_HALFS), rem = (int)(idx % WT_HALFS);
        int mi = rem / KAP, kl = rem % KAP;
        float v = 0.f;
        if (kl < KC) v = Wout[(long)mi * HH + c * KC + kl];
        d_Wpo[idx] = __float2half(v);
    }
    // biases (gate-interleaved: row = 4j+g)
    for (long idx = tid; idx < GG; idx += stride) {
        int row = (int)idx, j = row >> 2, g = row & 3;
        int sj = g * HH + j;
        d_bc1[row] = bih1[sj] + bhh1[sj];
        d_bc2[row] = bih2[sj] + bhh2[sj];
    }
    // x transposed: [t][kl][b] padded
    for (long idx = tid; idx < (long)TT * XT_HALFS; idx += stride) {
        int t = (int)(idx / XT_HALFS), rem = (int)(idx % XT_HALFS);
        int kl = rem / BP, b = rem % BP;
        float v = (b < BB) ? x[((long)b * TT + t) * 64 + kl] : 0.f;
        d_Xt[idx] = __float2half(v);
    }
    // zero state (incl. slack)
    for (long idx = tid; idx < (long)2 * HH * BP + 64 * BP; idx += stride) {
        d_H1t[idx] = __float2half(0.f);
        d_H2t[idx] = __float2half(0.f);
    }
    for (long idx = tid; idx < (long)HH * BB; idx += stride) {
        d_C1[idx] = 0.f;
        d_C2[idx] = 0.f;
    }
}

// ---------------- helpers ----------------
__device__ __forceinline__ void mbar_init(uint32_t mbar, uint32_t count) {
    asm volatile("mbarrier.init.shared.b64 [%0], %1;" :: "r"(mbar), "r"(count) : "memory");
}
__device__ __forceinline__ void mbar_expect_tx(uint32_t mbar, uint32_t bytes) {
    asm volatile("mbarrier.arrive.expect_tx.shared.b64 _, [%0], %1;" :: "r"(mbar), "r"(bytes) : "memory");
}
__device__ __forceinline__ void mbar_arrive(uint32_t mbar) {
    asm volatile("mbarrier.arrive.shared.b64 _, [%0];" :: "r"(mbar) : "memory");
}
__device__ __forceinline__ void mbar_wait(uint32_t mbar, uint32_t parity) {
    asm volatile(
        "{\n\t.reg .pred P;\n\t"
        "W_%=:\n\t"
        "mbarrier.try_wait.parity.acquire.cta.shared::cta.b64 P, [%0], %1;\n\t"
        "@!P bra W_%=;\n\t}"
        :: "r"(mbar), "r"(parity) : "memory");
}
__device__ __forceinline__ void bulk_g2s(uint32_t dst, const void* src, uint32_t bytes, uint32_t mbar) {
    asm volatile("cp.async.bulk.shared::cluster.global.mbarrier::complete_tx::bytes [%0], [%1], %2, [%3];"
                 :: "r"(dst), "l"(src), "r"(bytes), "r"(mbar) : "memory");
}
__device__ __forceinline__ void ldsm_x4(uint32_t* r, uint32_t addr) {
    asm volatile("ldmatrix.sync.aligned.m8n8.x4.shared.b16 {%0,%1,%2,%3}, [%4];"
                 : "=r"(r[0]), "=r"(r[1]), "=r"(r[2]), "=r"(r[3]) : "r"(addr));
}
__device__ __forceinline__ void ldsm_x4_t(uint32_t* r, uint32_t addr) {
    asm volatile("ldmatrix.sync.aligned.m8n8.x4.trans.shared.b16 {%0,%1,%2,%3}, [%4];"
                 : "=r"(r[0]), "=r"(r[1]), "=r"(r[2]), "=r"(r[3]) : "r"(addr));
}
__device__ __forceinline__ void mma16816(float* c, const uint32_t* a, uint32_t b0, uint32_t b1) {
    asm volatile(
        "mma.sync.aligned.m16n8k16.row.col.f32.f16.f16.f32 "
        "{%0,%1,%2,%3}, {%4,%5,%6,%7}, {%8,%9}, {%0,%1,%2,%3};\n"
        : "+f"(c[0]), "+f"(c[1]), "+f"(c[2]), "+f"(c[3])
        : "r"(a[0]), "r"(a[1]), "r"(a[2]), "r"(a[3]), "r"(b0), "r"(b1));
}
__device__ __forceinline__ float sigmoidf_(float v) { return 1.f / (1.f + expf(-v)); }

__device__ __forceinline__ void grid_barrier(unsigned target) {
    __threadfence();
    __syncthreads();
    if (threadIdx.x == 0) {
        atomicAdd(&g_bar, 1u);
        while (*(volatile unsigned*)&g_bar < target) { }
    }
    __syncthreads();
    __threadfence();
}

// ---------------- one GEMM tile (D[m=gates 64][n=batch 128]) + epilogue ----------------
// mode 0: L1 gates step t (nc=9, K=[x|h1(t-1)] padded)
// mode 1: L2 gates step s (nc=16, K=[h1(s)|h2(s-1)])
// mode 2: y proj step u   (nc=8,  K=h2(u))
__device__ __forceinline__ void do_tile(int mode, int step, int bi, char* smem,
        const float* __restrict__ b_out, float* __restrict__ out,
        int& cslot, unsigned& cc0, unsigned& cc1, unsigned& cc2,
        int& pslot, unsigned& pp0, unsigned& pp1, unsigned& pp2)
{
    const int tid = threadIdx.x;
    const int warp = tid >> 5, lane = tid & 31;
    const uint32_t smem_u32 = (uint32_t)__cvta_generic_to_shared(smem);
    const uint32_t MB_F = smem_u32 + NSTG * STAGE_BYTES;   // full barriers (tx)
    const uint32_t MB_E = MB_F + 32;                       // empty barriers (count 16)

    const int nc = (mode == 0) ? 9 : (mode == 1) ? 16 : 8;
    const int par = step & 1, parq = par ^ 1;
    const __half* Wt = (mode == 0) ? d_Wp1 + (long)bi * 9 * WT_HALFS
                     : (mode == 1) ? d_Wp2 + (long)bi * 16 * WT_HALFS
                                   : d_Wpo;

    // ---------------- producer warp (warp 16) ----------------
    if (warp == 16) {
        if (lane == 0) {
            for (int f = 0; f < nc; f++) {
                if (pp0 >= 1) mbar_wait(MB_E + 8 * pslot, (pp0 - 1) & 1);
                uint32_t st = smem_u32 + pslot * STAGE_BYTES;
                uint32_t bar = MB_F + 8 * pslot;
                mbar_expect_tx(bar, STAGE_BYTES);
                bulk_g2s(st, Wt + (long)f * WT_HALFS, ATILE_BYTES, bar);
                if (mode == 0) {
                    if (f == 0) {
                        bulk_g2s(st + ATILE_BYTES, d_Xt + (long)step * XT_HALFS, BHALF_BYTES, bar);
                        bulk_g2s(st + ATILE_BYTES + BHALF_BYTES,
                                 d_H1t + (long)parq * HH * BP, BHALF_BYTES, bar);
                    } else {
                        bulk_g2s(st + ATILE_BYTES,
                                 d_H1t + (long)parq * HH * BP + ((long)f * KC - 64) * BP,
                                 BTILE_BYTES, bar);
                    }
                } else if (mode == 1) {
                    const __half* act = (f < 8)
                        ? d_H1t + (long)par  * HH * BP + (long)f * KC * BP
                        : d_H2t + (long)parq * HH * BP + (long)(f - 8) * KC * BP;
                    bulk_g2s(st + ATILE_BYTES, act, BTILE_BYTES, bar);
                } else {
                    bulk_g2s(st + ATILE_BYTES,
                             d_H2t + (long)par * HH * BP + (long)f * KC * BP, BTILE_BYTES, bar);
                }
                unsigned t_ = pp0 + 1; pp0 = pp1; pp1 = pp2; pp2 = t_;
                pslot = (pslot == 2) ? 0 : pslot + 1;
            }
        }
    }

    // ---------------- compute warps: 2M x 2N x 4K, warp tile 32x64 ----------------
    const int wk = warp & 3;                    // K quarter: kk pair [2wk, 2wk+1]
    const int wm = (warp >> 2) & 1, wn = warp >> 3;   // wn in {0,1} (warp<16)
    const int g = lane >> 2, tg = lane & 3;
    const int mat = lane >> 3, r8 = lane & 7;

    // lane base offsets (halfs within stage)
    const int aoff = (wm * 32 + (mat & 1) * 8 + r8) * KAP + (mat >> 1) * 8 + wk * 32;
    const int boff = (wk * 32 + (mat & 1) * 8 + r8) * BP + wn * 64 + (mat >> 1) * 8;

    float acc[2][8][4];
#pragma unroll
    for (int i = 0; i < 2; i++)
#pragma unroll
        for (int j = 0; j < 8; j++)
#pragma unroll
            for (int k = 0; k < 4; k++) acc[i][j][k] = 0.f;

    if (warp < 16) {
        for (int c = 0; c < nc; c++) {
            mbar_wait(MB_F + 8 * cslot, cc0 & 1);
            uint32_t st = smem_u32 + cslot * STAGE_BYTES;
            uint32_t aB = st + 2 * aoff;
            uint32_t bB = st + ATILE_BYTES + 2 * boff;
#pragma unroll
            for (int k2 = 0; k2 < 2; k2++) {
                uint32_t fa[2][4], fb[4][4];
                ldsm_x4(fa[0], aB + 2 * (k2 * 16));
                ldsm_x4(fa[1], aB + 2 * (16 * KAP + k2 * 16));
#pragma unroll
                for (int q = 0; q < 4; q++)
                    ldsm_x4_t(fb[q], bB + 2 * (k2 * 16 * BP + 16 * q));
#pragma unroll
                for (int mi = 0; mi < 2; mi++)
#pragma unroll
                    for (int q = 0; q < 4; q++) {
                        mma16816(acc[mi][2 * q],     fa[mi], fb[q][0], fb[q][1]);
                        mma16816(acc[mi][2 * q + 1], fa[mi], fb[q][2], fb[q][3]);
                    }
            }
            if (lane == 0) mbar_arrive(MB_E + 8 * cslot);
            unsigned t_ = cc0 + 1; cc0 = cc1; cc1 = cc2; cc2 = t_;
            cslot = (cslot == 2) ? 0 : cslot + 1;
        }
    }
    __syncthreads();   // all slots drained; safe to alias stage smem

    // ---- stage gates to 4 fp32 buffers [64 m][132] (K-quarters separate) ----
    float* Gs = (float*)smem;
    if (warp < 16) {
        float* G = Gs + wk * GSB;
#pragma unroll
        for (int mi = 0; mi < 2; mi++)
#pragma unroll
            for (int nj = 0; nj < 8; nj++) {
                int m0 = wm * 32 + mi * 16 + g;
                int n0 = wn * 64 + nj * 8 + 2 * tg;
                G[m0 * 132 + n0]           = acc[mi][nj][0];
                G[m0 * 132 + n0 + 1]       = acc[mi][nj][1];
                G[(m0 + 8) * 132 + n0]     = acc[mi][nj][2];
                G[(m0 + 8) * 132 + n0 + 1] = acc[mi][nj][3];
            }
    }
    __syncthreads();

    if (mode == 2) {
        if (tid < 512) {
#pragma unroll
            for (int i = 0; i < 16; i++) {
                int e = tid + i * 512;                   // 8192 = 128 b x 64 o
                int b = e >> 6, o = e & 63;
                const float* gq = Gs + o * 132 + b;
                out[((long)b * TT + step) * OO + o] =
                    gq[0] + gq[GSB] + gq[2 * GSB] + gq[3 * GSB] + b_out[o];
            }
        }
        return;
    }

    if (tid < 512) {
        const float* bc = (mode == 0) ? d_bc1 : d_bc2;
        float* C        = (mode == 0) ? d_C1 : d_C2;
        __half* Hdst    = ((mode == 0) ? d_H1t : d_H2t) + (long)par * HH * BP;
        const int m0g   = bi * 64;
#pragma unroll
        for (int i = 0; i < 4; i++) {
            int e = tid + i * 512;                       // 2048 = 16 j x 128 b
            int jl = e >> 7, b = e & 127;
            const float* gq = Gs + (4 * jl) * 132 + b;
            float gi = gq[0]   + gq[GSB]       + gq[2 * GSB]       + gq[3 * GSB]       + bc[m0g + 4 * jl + 0];
            float gf = gq[132] + gq[GSB + 132] + gq[2 * GSB + 132] + gq[3 * GSB + 132] + bc[m0g + 4 * jl + 1];
            float gg = gq[264] + gq[GSB + 264] + gq[2 * GSB + 264] + gq[3 * GSB + 264] + bc[m0g + 4 * jl + 2];
            float go = gq[396] + gq[GSB + 396] + gq[2 * GSB + 396] + gq[3 * GSB + 396] + bc[m0g + 4 * jl + 3];
            float iv = sigmoidf_(gi);
            float fv = sigmoidf_(gf);
            float gv = tanhf(gg);
            float ov = sigmoidf_(go);
            int j = bi * 16 + jl;
            float cold = C[j * BB + b];
            float cn = fv * cold + iv * gv;
            C[j * BB + b] = cn;
            Hdst[j * BP + b] = __float2half(ov * tanhf(cn));
        }
    }
}

// ---------------- persistent kernel ----------------
// Phase P(t): L1(t) [bx 0..63] || L2(t-1) [bx 64..127] || y(t-2) [bx 128]
__global__ __launch_bounds__(NTHR, 1)
void lstm_persistent(const float* __restrict__ b_out, float* __restrict__ out)
{
    extern __shared__ char smem[];
    const int tid = threadIdx.x;
    const uint32_t smem_u32 = (uint32_t)__cvta_generic_to_shared(smem);
    const uint32_t MB_F = smem_u32 + NSTG * STAGE_BYTES;
    const uint32_t MB_E = MB_F + 32;

    if (tid == 0) {
#pragma unroll
        for (int s = 0; s < NSTG; s++) {
            mbar_init(MB_F + 8 * s, 1);
            mbar_init(MB_E + 8 * s, 16);
        }
        asm volatile("fence.proxy.async.shared::cta;" ::: "memory");
    }
    __syncthreads();

    const int bx = blockIdx.x;
    unsigned target = 0;
    int cslot = 0, pslot = 0;
    unsigned cc0 = 0, cc1 = 0, cc2 = 0, pp0 = 0, pp1 = 0, pp2 = 0;

    for (int t = 0; t <= TT + 1; t++) {
        if (bx < 64) {
            if (t < TT)
                do_tile(0, t, bx, smem, b_out, out, cslot, cc0, cc1, cc2, pslot, pp0, pp1, pp2);
        } else if (bx < 128) {
            if (t >= 1 && t <= TT)
                do_tile(1, t - 1, bx - 64, smem, b_out, out, cslot, cc0, cc1, cc2, pslot, pp0, pp1, pp2);
        } else {
            if (t >= 2)
                do_tile(2, t - 2, 0, smem, b_out, out, cslot, cc0, cc1, cc2, pslot, pp0, pp1, pp2);
        }
        target += NB;
        grid_barrier(target);
    }
}

// ---------------- launch ----------------
extern "C" void kernel_launch(void* const* d_in, const int* in_sizes, int n_in,
                              void* d_out, int out_size)
{
    const float* x     = (const float*)d_in[0];
    const float* Wih1  = (const float*)d_in[1];
    const float* Whh1  = (const float*)d_in[2];
    const float* bih1  = (const float*)d_in[3];
    const float* bhh1  = (const float*)d_in[4];
    const float* Wih2  = (const float*)d_in[5];
    const float* Whh2  = (const float*)d_in[6];
    const float* bih2  = (const float*)d_in[7];
    const float* bhh2  = (const float*)d_in[8];
    const float* Wout  = (const float*)d_in[9];
    const float* bout  = (const float*)d_in[10];
    float* out = (float*)d_out;

    cudaFuncSetAttribute(lstm_persistent,
                         cudaFuncAttributeMaxDynamicSharedMemorySize, SMEM_BYTES);

    init_kernel<<<2048, 256>>>(x, Wih1, Whh1, bih1, bhh1, Wih2, Whh2, bih2, bhh2, Wout);
    lstm_persistent<<<NB, NTHR, SMEM_BYTES>>>(bout, out);
}